// round 9
// baseline (speedup 1.0000x reference)
#include <cuda_runtime.h>

// ---------------------------------------------------------------------------
// SpectralConv2d (FNO). B=8, C=64, H=W=256, M1=M2=32. Two branches.
// v9: v7 structure (serial branches) + s1s2 h-split (2 blocks/ch, partial XF
//     planes summed inside s3 staging).
// ---------------------------------------------------------------------------

namespace {
constexpr int NCH = 512;           // B*C
constexpr size_t HALFSTRIDE = (size_t)NCH * 4096;  // floats per h-half plane
}

typedef unsigned long long ull;

__device__ __forceinline__ ull pk2(float lo, float hi) {
    ull r; asm("mov.b64 %0, {%1,%2};" : "=l"(r) : "f"(lo), "f"(hi)); return r;
}
__device__ __forceinline__ ull ffma2(ull a, ull b, ull c) {
    ull d; asm("fma.rn.f32x2 %0, %1, %2, %3;" : "=l"(d) : "l"(a), "l"(b), "l"(c)); return d;
}
__device__ __forceinline__ ull add2(ull a, ull b) {
    ull d; asm("add.rn.f32x2 %0, %1, %2;" : "=l"(d) : "l"(a), "l"(b)); return d;
}
__device__ __forceinline__ float2 upk(ull v) {
    float2 r; asm("mov.b64 {%0,%1}, %2;" : "=f"(r.x), "=f"(r.y) : "l"(v)); return r;
}

__device__ float g_twr[256];
__device__ float g_twi[256];
__device__ float g_Cc[128 * 32];             // cos(2pi k2 w'/256) [w'][k2]
__device__ float g_Cs[128 * 32];             // -sin               [w'][k2]
__device__ float g_Fc[32 * 128];             // sc*(k2?2cos:1)     [k2][w']
__device__ float g_Fs[32 * 128];             // k2? -2sc*sin : 0   [k2][w']
__device__ float g_XF[2 * NCH * 4096];       // two h-half partial planes
__device__ float g_Y [NCH * 4096];

// ---------------- init ------------------------------------------------------
__global__ void k_init() {
    int idx = blockIdx.x * 256 + threadIdx.x;
    const float sc = 1.0f / 65536.0f;
    if (idx < 256) {
        double s, c;
        sincospi(-2.0 * (double)idx / 256.0, &s, &c);
        g_twr[idx] = (float)c;
        g_twi[idx] = (float)s;
    } else if (idx < 256 + 4096) {
        int j = idx - 256;
        int wp = j >> 5, k2 = j & 31;
        int ang = (k2 * wp) & 255;
        double s, c;
        sincospi(-2.0 * (double)ang / 256.0, &s, &c);
        g_Cc[wp * 32 + k2] = (float)c;
        g_Cs[wp * 32 + k2] = (float)s;
    } else if (idx < 256 + 8192) {
        int j = idx - 4352;
        int k2 = j >> 7, wp = j & 127;
        int ang = (k2 * wp) & 255;
        double s, c;
        sincospi(-2.0 * (double)ang / 256.0, &s, &c);
        g_Fc[k2 * 128 + wp] = (k2 == 0) ? sc : 2.0f * sc * (float)c;
        g_Fs[k2 * 128 + wp] = (k2 == 0) ? 0.0f : 2.0f * sc * (float)s;
    }
}

// ---------------- fused stage 1+2 (256 threads, h-split: 2 blocks/ch) -------
// block = (ch, half); processes h-chunks {2*half, 2*half+1}; writes partial XF.
__global__ __launch_bounds__(256) void k_s1s2(const float* __restrict__ x, int trans) {
    __shared__ ull bufu[3104];            // A-buffers / Tr,Ti planes (aliased)
    __shared__ float str[256], sti[256];
    __shared__ float sx128[64];
    float* buf = (float*)bufu;
    float* xe  = buf;                     // [32 w'][65]
    float* xo  = buf + 2080;
    float* sCc = buf + 4160;              // [32 kk][32 k2]
    float* sCs = buf + 5184;
    ull* sTr = bufu;                      // [64 h][18 ull]
    ull* sTi = bufu + 1152;

    int t    = threadIdx.x;
    int ch   = blockIdx.x >> 1;
    int half = blockIdx.x & 1;
    const float* xc = x + (size_t)ch * 65536;
    str[t] = g_twr[t];
    sti[t] = g_twi[t];

    int rp = t >> 3;                      // 0..31
    int kg = t & 7;                       // k2 group of 4 (2 ull)
    int m  = rp ? rp : 32;                // twiddle base multiplier
    ull Aq[2], Bq[2], Cq[2], Dq[2], SrA[2], SiA[2];
#pragma unroll
    for (int q = 0; q < 2; q++) { Aq[q]=0ull; Bq[q]=0ull; Cq[q]=0ull; Dq[q]=0ull; SrA[q]=0ull; SiA[q]=0ull; }

    for (int hc = half * 2; hc < half * 2 + 2; hc++) {
        ull Tr0[2], Ti0[2], Tr1[2], Ti1[2];
#pragma unroll
        for (int q = 0; q < 2; q++) { Tr0[q]=0ull; Ti0[q]=0ull; Tr1[q]=0ull; Ti1[q]=0ull; }

        for (int kc = 0; kc < 4; kc++) {
            __syncthreads();
            ((float4*)sCc)[t] = ((const float4*)(g_Cc + kc * 1024))[t];
            ((float4*)sCs)[t] = ((const float4*)(g_Cs + kc * 1024))[t];
#pragma unroll
            for (int q = 0; q < 8; q++) {
                int flat = q * 256 + t;
                int wl, row;
                if (!trans) { wl = flat & 31; row = flat >> 5; }
                else        { row = flat & 63; wl = flat >> 6; }
                int wp = kc * 32 + wl;
                float xv, xm;
                if (!trans) {
                    xv = xc[(hc * 64 + row) * 256 + wp];
                    xm = (wp == 0) ? 0.f : xc[(hc * 64 + row) * 256 + 256 - wp];
                } else {
                    xv = xc[wp * 256 + hc * 64 + row];
                    xm = (wp == 0) ? 0.f : xc[(256 - wp) * 256 + hc * 64 + row];
                }
                xe[wl * 65 + row] = (wp == 0) ? xv : xv + xm;
                xo[wl * 65 + row] = (wp == 0) ? 0.f : xv - xm;
                if (wp == 0)
                    sx128[row] = (!trans) ? xc[(hc * 64 + row) * 256 + 128]
                                          : xc[128 * 256 + hc * 64 + row];
            }
            __syncthreads();
#pragma unroll 4
            for (int kk = 0; kk < 32; kk++) {
                float a0e = xe[kk * 65 + rp];
                float a1e = xe[kk * 65 + rp + 32];
                float a0o = xo[kk * 65 + rp];
                float a1o = xo[kk * 65 + rp + 32];
                ull pa0e = pk2(a0e, a0e), pa1e = pk2(a1e, a1e);
                ull pa0o = pk2(a0o, a0o), pa1o = pk2(a1o, a1o);
                ulonglong2 c01 = *(const ulonglong2*)(sCc + kk * 32 + kg * 4);
                ulonglong2 s01 = *(const ulonglong2*)(sCs + kk * 32 + kg * 4);
                Tr0[0] = ffma2(pa0e, c01.x, Tr0[0]); Tr0[1] = ffma2(pa0e, c01.y, Tr0[1]);
                Tr1[0] = ffma2(pa1e, c01.x, Tr1[0]); Tr1[1] = ffma2(pa1e, c01.y, Tr1[1]);
                Ti0[0] = ffma2(pa0o, s01.x, Ti0[0]); Ti0[1] = ffma2(pa0o, s01.y, Ti0[1]);
                Ti1[0] = ffma2(pa1o, s01.x, Ti1[0]); Ti1[1] = ffma2(pa1o, s01.y, Ti1[1]);
            }
        }
        {   // x[128] parity term (pairs are (even k2, odd k2))
            const ull PM = pk2(1.f, -1.f);
            ull px0 = pk2(sx128[rp], sx128[rp]);
            ull px1 = pk2(sx128[rp + 32], sx128[rp + 32]);
#pragma unroll
            for (int q = 0; q < 2; q++) {
                Tr0[q] = ffma2(px0, PM, Tr0[q]);
                Tr1[q] = ffma2(px1, PM, Tr1[q]);
            }
        }
        __syncthreads();
#pragma unroll
        for (int q = 0; q < 2; q++) {
            sTr[rp * 18 + kg * 2 + q]        = Tr0[q];
            sTi[rp * 18 + kg * 2 + q]        = Ti0[q];
            sTr[(rp + 32) * 18 + kg * 2 + q] = Tr1[q];
            sTi[(rp + 32) * 18 + kg * 2 + q] = Ti1[q];
        }
        __syncthreads();
        // Phase B: accumulate A,B',C',D at base angle m*h (h within this half)
#pragma unroll 2
        for (int hh = 0; hh < 64; hh++) {
            int h   = hc * 64 + hh;
            int idx = (m * h) & 255;
            float c = str[idx], s = sti[idx];
            ull cp = pk2(c, c), sp = pk2(s, s);
            ulonglong2 tr = *(const ulonglong2*)(sTr + hh * 18 + kg * 2);
            ulonglong2 ti = *(const ulonglong2*)(sTi + hh * 18 + kg * 2);
            Aq[0] = ffma2(tr.x, cp, Aq[0]); Cq[0] = ffma2(tr.x, sp, Cq[0]);
            Dq[0] = ffma2(ti.x, cp, Dq[0]); Bq[0] = ffma2(ti.x, sp, Bq[0]);
            Aq[1] = ffma2(tr.y, cp, Aq[1]); Cq[1] = ffma2(tr.y, sp, Cq[1]);
            Dq[1] = ffma2(ti.y, cp, Dq[1]); Bq[1] = ffma2(ti.y, sp, Bq[1]);
            if (rp == 0) {
                SrA[0] = add2(SrA[0], tr.x); SrA[1] = add2(SrA[1], tr.y);
                SiA[0] = add2(SiA[0], ti.x); SiA[1] = add2(SiA[1], ti.y);
            }
        }
    }
    // combine (linear in A..D, so per-half partials sum exactly in s3)
    {
        const ull M1 = pk2(-1.f, -1.f);
        float4* XF4 = (float4*)(g_XF + (size_t)half * HALFSTRIDE + (size_t)ch * 4096);
        int jhi = rp ? (64 - rp) : 32;
#pragma unroll
        for (int q = 0; q < 2; q++) {
            ull rhi = add2(Aq[q], Bq[q]);
            ull ihi = ffma2(Cq[q], M1, Dq[q]);
            ull rlo = rp ? ffma2(Bq[q], M1, Aq[q]) : SrA[q];
            ull ilo = rp ? add2(Dq[q], Cq[q])      : SiA[q];
            float2 a = upk(rlo), b = upk(ilo);
            float2 cc = upk(rhi), d = upk(ihi);
            XF4[rp * 16 + kg * 2 + q]  = make_float4(a.x, b.x, a.y, b.y);
            XF4[jhi * 16 + kg * 2 + q] = make_float4(cc.x, d.x, cc.y, d.y);
        }
    }
}

// ---------------- stage 3: mode mix (sums the two XF partials) --------------
__global__ __launch_bounds__(256) void k_s3(const float* __restrict__ wAr,
                                            const float* __restrict__ wAi,
                                            const float* __restrict__ wBr,
                                            const float* __restrict__ wBi) {
    __shared__ ull sp[4096];              // sxr 2048 | sxi 2048 (32 KB)
    float* sxr = (float*)sp;
    float* sxi = (float*)(sp + 2048);
    int t  = threadIdx.x;
    int j  = blockIdx.x >> 3;
    int ot = blockIdx.x & 7;
    int o  = ot * 8 + (t >> 5);
    int lane = t & 31;
    int bh   = lane >> 4;
    int k2a  = (lane & 15) * 2;
    const float* wr; const float* wi; int jw;
    if (j < 32) { wr = wAr; wi = wAi; jw = j; }
    else        { wr = wBr; wi = wBi; jw = j - 32; }
    ull yrp[4], yip[4];
#pragma unroll
    for (int b = 0; b < 4; b++) { yrp[b] = 0ull; yip[b] = 0ull; }
    const float2* XF0 = (const float2*)g_XF;
    const float2* XF1 = (const float2*)(g_XF + HALFSTRIDE);

    for (int ic = 0; ic < 4; ic++) {
        __syncthreads();
#pragma unroll
        for (int q = 0; q < 16; q++) {
            int flat = q * 256 + t;
            int kl = flat & 31;
            int ii = (flat >> 5) & 15;
            int b  = flat >> 9;
            size_t idx = ((size_t)(b * 64 + ic * 16 + ii) * 64 + j) * 32 + kl;
            float2 v0 = XF0[idx];
            float2 v1 = XF1[idx];
            sxr[(b * 16 + ii) * 32 + kl] = v0.x + v1.x;
            sxi[(b * 16 + ii) * 32 + kl] = v0.y + v1.y;
        }
        __syncthreads();
#pragma unroll 4
        for (int ii = 0; ii < 16; ii++) {
            int i = ic * 16 + ii;
            size_t wb = (size_t)(i * 64 + o) * 1024 + jw * 32 + k2a;
            float2 wre2 = *(const float2*)(wr + wb);
            float2 wim2 = *(const float2*)(wi + wb);
            ull wrp  = pk2(wre2.x, wre2.y);
            ull wip  = pk2(wim2.x, wim2.y);
            ull nwip = pk2(-wim2.x, -wim2.y);
#pragma unroll
            for (int bb = 0; bb < 4; bb++) {
                int b = bh * 4 + bb;
                ull xrp = *(const ull*)(sxr + (b * 16 + ii) * 32 + k2a);
                ull xip = *(const ull*)(sxi + (b * 16 + ii) * 32 + k2a);
                yrp[bb] = ffma2(xrp, wrp, yrp[bb]);  yrp[bb] = ffma2(xip, nwip, yrp[bb]);
                yip[bb] = ffma2(xrp, wip, yip[bb]);  yip[bb] = ffma2(xip, wrp,  yip[bb]);
            }
        }
    }
#pragma unroll
    for (int bb = 0; bb < 4; bb++) {
        int b = bh * 4 + bb;
        float2 r = upk(yrp[bb]), im = upk(yip[bb]);
        *(float4*)(g_Y + (((size_t)(b * 64 + o) * 64 + j) * 32 + k2a) * 2) =
            make_float4(r.x, im.x, r.y, im.y);
    }
}

// ---------------- fused stage 4+5 (unchanged from v7) -----------------------
__global__ __launch_bounds__(256) void k_s4s5(float* __restrict__ out) {
    __shared__ float zsA[64 * 68];
    __shared__ float zsB[64 * 68];
    __shared__ ull reg2u[2304];           // sY planes (E/O transformed), later F staging
    __shared__ float str[256], sti[256];
    float* reg2 = (float*)reg2u;
    int t  = threadIdx.x;
    int ch = blockIdx.x >> 1;
    int g0 = (blockIdx.x & 1) << 6;
    str[t] = g_twr[t];
    sti[t] = g_twi[t];

    float* pYr = reg2;                    // [j][36]
    float* pYi = reg2 + 2304;
    {   // stage Y -> deinterleaved planes
        const float2* Yg = (const float2*)(g_Y + (size_t)ch * 4096);
#pragma unroll
        for (int q = 0; q < 8; q++) {
            int flat = q * 256 + t;
            int jj = flat >> 5, kl = flat & 31;
            float2 v = Yg[flat];
            pYr[jj * 36 + kl] = v.x;
            pYi[jj * 36 + kl] = v.y;
        }
    }
    __syncthreads();
    {   // E/O transform in place: row a <- Y[a]+Y[64-a], row 64-a <- Y[a]-Y[64-a]
#pragma unroll
        for (int q = 0; q < 4; q++) {
            int flat = q * 256 + t;
            if (flat < 992) {
                int a = (flat >> 5) + 1;
                int col = flat & 31;
                float ya = pYr[a * 36 + col], yb = pYr[(64 - a) * 36 + col];
                pYr[a * 36 + col] = ya + yb;
                pYr[(64 - a) * 36 + col] = ya - yb;
                float za = pYi[a * 36 + col], zb = pYi[(64 - a) * 36 + col];
                pYi[a * 36 + col] = za + zb;
                pYi[(64 - a) * 36 + col] = za - zb;
            }
        }
    }
    __syncthreads();
    ull* sYr = reg2u;
    ull* sYi = reg2u + 1152;

    int hp = t >> 3;                      // 0..31
    int kg = t & 7;                       // k2 group of 4 (2 ull)
    int hA = g0 + hp;
    ull ze0r[2], ze0i[2], zo0r[2], zo0i[2];   // h = hA
    ull ze1r[2], ze1i[2], zo1r[2], zo1i[2];   // h = hA+32
#pragma unroll
    for (int q = 0; q < 2; q++) {
        ze0r[q]=0ull; ze0i[q]=0ull; zo0r[q]=0ull; zo0i[q]=0ull;
        ze1r[q]=0ull; ze1i[q]=0ull; zo1r[q]=0ull; zo1i[q]=0ull;
    }

#define PBODY(A, R0, I0, R1, I1) { \
    int ia = ((A) * hA) & 255; \
    int ib = (ia + (A) * 32) & 255; \
    float c0 = str[ia], t0 = sti[ia]; \
    float c1 = str[ib], t1 = sti[ib]; \
    ull c0p = pk2(c0, c0), t0p = pk2(t0, t0), n0p = pk2(-t0, -t0); \
    ull c1p = pk2(c1, c1), t1p = pk2(t1, t1), n1p = pk2(-t1, -t1); \
    ulonglong2 er  = *(const ulonglong2*)(sYr + (A) * 18 + kg * 2); \
    ulonglong2 ei  = *(const ulonglong2*)(sYi + (A) * 18 + kg * 2); \
    ulonglong2 orr = *(const ulonglong2*)(sYr + (64 - (A)) * 18 + kg * 2); \
    ulonglong2 oii = *(const ulonglong2*)(sYi + (64 - (A)) * 18 + kg * 2); \
    R0[0] = ffma2(er.x, c0p, R0[0]);  R0[0] = ffma2(oii.x, t0p, R0[0]); \
    I0[0] = ffma2(ei.x, c0p, I0[0]);  I0[0] = ffma2(orr.x, n0p, I0[0]); \
    R0[1] = ffma2(er.y, c0p, R0[1]);  R0[1] = ffma2(oii.y, t0p, R0[1]); \
    I0[1] = ffma2(ei.y, c0p, I0[1]);  I0[1] = ffma2(orr.y, n0p, I0[1]); \
    R1[0] = ffma2(er.x, c1p, R1[0]);  R1[0] = ffma2(oii.x, t1p, R1[0]); \
    I1[0] = ffma2(ei.x, c1p, I1[0]);  I1[0] = ffma2(orr.x, n1p, I1[0]); \
    R1[1] = ffma2(er.y, c1p, R1[1]);  R1[1] = ffma2(oii.y, t1p, R1[1]); \
    I1[1] = ffma2(ei.y, c1p, I1[1]);  I1[1] = ffma2(orr.y, n1p, I1[1]); }

#pragma unroll 3
    for (int ap = 0; ap < 15; ap++) {
        PBODY(2 * ap + 1, zo0r, zo0i, zo1r, zo1i)
        PBODY(2 * ap + 2, ze0r, ze0i, ze1r, ze1i)
    }
    PBODY(31, zo0r, zo0i, zo1r, zo1i)
#undef PBODY

    {   // j=0 (k1=0, even): constant contribution Y0 to both h regs
        ulonglong2 y0r = *(const ulonglong2*)(sYr + kg * 2);
        ulonglong2 y0i = *(const ulonglong2*)(sYi + kg * 2);
        ze0r[0] = add2(ze0r[0], y0r.x); ze0r[1] = add2(ze0r[1], y0r.y);
        ze0i[0] = add2(ze0i[0], y0i.x); ze0i[1] = add2(ze0i[1], y0i.y);
        ze1r[0] = add2(ze1r[0], y0r.x); ze1r[1] = add2(ze1r[1], y0r.y);
        ze1i[0] = add2(ze1i[0], y0i.x); ze1i[1] = add2(ze1i[1], y0i.y);
    }
    {   // j=32 (k1=-32, even): e^{-i32h} -- same angle for hA and hA+32
        int i32 = (32 * hA) & 255;
        float c = str[i32], tv = sti[i32];
        ull cp = pk2(c, c), tp = pk2(tv, tv), np = pk2(-tv, -tv);
        ulonglong2 y2r = *(const ulonglong2*)(sYr + 32 * 18 + kg * 2);
        ulonglong2 y2i = *(const ulonglong2*)(sYi + 32 * 18 + kg * 2);
#pragma unroll
        for (int q = 0; q < 2; q++) {
            ull r2v = q ? y2r.y : y2r.x;
            ull i2v = q ? y2i.y : y2i.x;
            ze0r[q] = ffma2(r2v, cp, ze0r[q]);  ze0r[q] = ffma2(i2v, np, ze0r[q]);
            ze0i[q] = ffma2(i2v, cp, ze0i[q]);  ze0i[q] = ffma2(r2v, tp, ze0i[q]);
            ze1r[q] = ffma2(r2v, cp, ze1r[q]);  ze1r[q] = ffma2(i2v, np, ze1r[q]);
            ze1i[q] = ffma2(i2v, cp, ze1i[q]);  ze1i[q] = ffma2(r2v, tp, ze1i[q]);
        }
    }

    // combine parity partials -> both h tiles
    {
        const ull M1 = pk2(-1.f, -1.f);
#pragma unroll
        for (int q = 0; q < 2; q++) {
            int c2 = 2 * (kg * 4 + 2 * q);
            float2 ra, ia, rb, ib;
            ra = upk(add2(ze0r[q], zo0r[q]));  ia = upk(add2(ze0i[q], zo0i[q]));
            rb = upk(ffma2(zo0r[q], M1, ze0r[q]));  ib = upk(ffma2(zo0i[q], M1, ze0i[q]));
            zsA[c2 * 68 + hp]       = ra.x; zsA[(c2 + 1) * 68 + hp] = ia.x;
            zsA[(c2 + 2) * 68 + hp] = ra.y; zsA[(c2 + 3) * 68 + hp] = ia.y;
            zsB[c2 * 68 + hp]       = rb.x; zsB[(c2 + 1) * 68 + hp] = ib.x;
            zsB[(c2 + 2) * 68 + hp] = rb.y; zsB[(c2 + 3) * 68 + hp] = ib.y;
            ra = upk(add2(ze1r[q], zo1r[q]));  ia = upk(add2(ze1i[q], zo1i[q]));
            rb = upk(ffma2(zo1r[q], M1, ze1r[q]));  ib = upk(ffma2(zo1i[q], M1, ze1i[q]));
            zsA[c2 * 68 + hp + 32]       = ra.x; zsA[(c2 + 1) * 68 + hp + 32] = ia.x;
            zsA[(c2 + 2) * 68 + hp + 32] = ra.y; zsA[(c2 + 3) * 68 + hp + 32] = ia.y;
            zsB[c2 * 68 + hp + 32]       = rb.x; zsB[(c2 + 1) * 68 + hp + 32] = ib.x;
            zsB[(c2 + 2) * 68 + hp + 32] = rb.y; zsB[(c2 + 3) * 68 + hp + 32] = ib.y;
        }
    }
    __syncthreads();

    // w=128 columns for both tiles
    if (t < 128) {
        int tile = t >> 6;
        int row  = t & 63;
        const float* zz = tile ? zsB : zsA;
        float s = zz[row];
#pragma unroll
        for (int k2 = 1; k2 < 32; k2++)
            s += ((k2 & 1) ? -2.f : 2.f) * zz[2 * k2 * 68 + row];
        out[((size_t)ch * 256 + g0 + tile * 128 + row) * 256 + 128] = s * (1.f / 65536.f);
    }

    // Phase B: folded inverse-w on both tiles
    int hg = t >> 4;                      // 0..15 -> 4 h rows
    int wg = t & 15;                      // 4 w' cols
    const float4* FcG = (const float4*)g_Fc;
    const float4* FsG = (const float4*)g_Fs;
    const ull M1 = pk2(-1.f, -1.f);
    for (int wt = 0; wt < 2; wt++) {
        __syncthreads();
        float4* fd = (float4*)reg2;
#pragma unroll
        for (int q = 0; q < 2; q++) {
            int flat = q * 256 + t;
            int k2 = flat >> 4, u = flat & 15;
            fd[k2 * 16 + u]       = FcG[k2 * 32 + wt * 16 + u];
            fd[512 + k2 * 16 + u] = FsG[k2 * 32 + wt * 16 + u];
        }
        __syncthreads();
        for (int tile = 0; tile < 2; tile++) {
            const float* zs = tile ? zsB : zsA;
            int hbase = g0 + tile * 128;
            ull P[8], Q[8];
#pragma unroll
            for (int q = 0; q < 8; q++) { P[q] = 0ull; Q[q] = 0ull; }
#pragma unroll 4
            for (int k2 = 0; k2 < 32; k2++) {
                float4 a = *(const float4*)(zs + (2 * k2) * 68 + hg * 4);
                float4 b = *(const float4*)(zs + (2 * k2 + 1) * 68 + hg * 4);
                const float* fp = reg2 + k2 * 64 + wg * 4;
                ulonglong2 f = *(const ulonglong2*)fp;
                ulonglong2 g = *(const ulonglong2*)(fp + 2048);
                ull pr, pi;
#define BROW(R, AV, BV) \
                pr = pk2(AV, AV); pi = pk2(BV, BV); \
                P[R*2+0] = ffma2(pr, f.x, P[R*2+0]); P[R*2+1] = ffma2(pr, f.y, P[R*2+1]); \
                Q[R*2+0] = ffma2(pi, g.x, Q[R*2+0]); Q[R*2+1] = ffma2(pi, g.y, Q[R*2+1]);
                BROW(0, a.x, b.x) BROW(1, a.y, b.y) BROW(2, a.z, b.z) BROW(3, a.w, b.w)
#undef BROW
            }
#pragma unroll
            for (int r = 0; r < 4; r++) {
                int hloc = hg * 4 + r;
                float* orow = out + ((size_t)ch * 256 + hbase + hloc) * 256;
                int wbase = wt * 64 + wg * 4;
                ull A0 = add2(P[r * 2], Q[r * 2]);
                ull A1 = add2(P[r * 2 + 1], Q[r * 2 + 1]);
                ull B0 = ffma2(Q[r * 2], M1, P[r * 2]);
                ull B1 = ffma2(Q[r * 2 + 1], M1, P[r * 2 + 1]);
                float2 fa0 = upk(A0), fa1 = upk(A1);
                float2 fb0 = upk(B0), fb1 = upk(B1);
                *(float4*)(orow + wbase) = make_float4(fa0.x, fa0.y, fa1.x, fa1.y);
                float bw[4] = {fb0.x, fb0.y, fb1.x, fb1.y};
#pragma unroll
                for (int i = 0; i < 4; i++) {
                    int wv = wbase + i;
                    if (wv) orow[256 - wv] = bw[i];
                }
            }
        }
    }
}

// ---------------------------------------------------------------------------
extern "C" void kernel_launch(void* const* d_in, const int* in_sizes, int n_in,
                              void* d_out, int out_size) {
    const float* x   = (const float*)d_in[0];
    const float* w1r = (const float*)d_in[1];
    const float* w1i = (const float*)d_in[2];
    const float* w2r = (const float*)d_in[3];
    const float* w2i = (const float*)d_in[4];
    const float* w3r = (const float*)d_in[5];
    const float* w3i = (const float*)d_in[6];
    const float* w4r = (const float*)d_in[7];
    const float* w4i = (const float*)d_in[8];
    float* out = (float*)d_out;

    k_init<<<34, 256>>>();

    // ---- branch x ----
    k_s1s2<<<1024, 256>>>(x, 0);
    k_s3<<<512, 256>>>(w1r, w1i, w2r, w2i);
    k_s4s5<<<1024, 256>>>(out);

    // ---- branch x^T ----
    k_s1s2<<<1024, 256>>>(x, 1);
    k_s3<<<512, 256>>>(w3r, w3i, w4r, w4i);
    k_s4s5<<<1024, 256>>>(out + (size_t)NCH * 65536);
}

// round 14
// speedup vs baseline: 1.4574x; 1.4574x over previous
#include <cuda_runtime.h>

// ---------------------------------------------------------------------------
// SpectralConv2d (FNO). B=8, C=64, H=W=256, M1=M2=32. Two branches.
// v10: v7 + s4s5 Phase-B tile merge (shared F twiddle loads across both
// h-tiles; 2 w'/thread x 4 wt chunks keeps registers flat).
// ---------------------------------------------------------------------------

namespace {
constexpr int NCH = 512;           // B*C
}

typedef unsigned long long ull;

__device__ __forceinline__ ull pk2(float lo, float hi) {
    ull r; asm("mov.b64 %0, {%1,%2};" : "=l"(r) : "f"(lo), "f"(hi)); return r;
}
__device__ __forceinline__ ull ffma2(ull a, ull b, ull c) {
    ull d; asm("fma.rn.f32x2 %0, %1, %2, %3;" : "=l"(d) : "l"(a), "l"(b), "l"(c)); return d;
}
__device__ __forceinline__ ull add2(ull a, ull b) {
    ull d; asm("add.rn.f32x2 %0, %1, %2;" : "=l"(d) : "l"(a), "l"(b)); return d;
}
__device__ __forceinline__ float2 upk(ull v) {
    float2 r; asm("mov.b64 {%0,%1}, %2;" : "=f"(r.x), "=f"(r.y) : "l"(v)); return r;
}

__device__ float g_twr[256];
__device__ float g_twi[256];
__device__ float g_Cc[128 * 32];             // cos(2pi k2 w'/256) [w'][k2]
__device__ float g_Cs[128 * 32];             // -sin               [w'][k2]
__device__ float g_Fc[32 * 128];             // sc*(k2?2cos:1)     [k2][w']
__device__ float g_Fs[32 * 128];             // k2? -2sc*sin : 0   [k2][w']
__device__ float g_XF[NCH * 64 * 32 * 2];
__device__ float g_Y [NCH * 64 * 32 * 2];

// ---------------- init ------------------------------------------------------
__global__ void k_init() {
    int idx = blockIdx.x * 256 + threadIdx.x;
    const float sc = 1.0f / 65536.0f;
    if (idx < 256) {
        double s, c;
        sincospi(-2.0 * (double)idx / 256.0, &s, &c);
        g_twr[idx] = (float)c;
        g_twi[idx] = (float)s;
    } else if (idx < 256 + 4096) {
        int j = idx - 256;
        int wp = j >> 5, k2 = j & 31;
        int ang = (k2 * wp) & 255;
        double s, c;
        sincospi(-2.0 * (double)ang / 256.0, &s, &c);
        g_Cc[wp * 32 + k2] = (float)c;
        g_Cs[wp * 32 + k2] = (float)s;
    } else if (idx < 256 + 8192) {
        int j = idx - 4352;
        int k2 = j >> 7, wp = j & 127;
        int ang = (k2 * wp) & 255;
        double s, c;
        sincospi(-2.0 * (double)ang / 256.0, &s, &c);
        g_Fc[k2 * 128 + wp] = (k2 == 0) ? sc : 2.0f * sc * (float)c;
        g_Fs[k2 * 128 + wp] = (k2 == 0) ? 0.0f : 2.0f * sc * (float)s;
    }
}

// ---------------- fused stage 1+2 (256 threads) -----------------------------
// Phase A: thread = (row-pair rp in {rp,rp+32}, k2-group kg of 4).
// Phase B (+-k paired): thread rp covers j=rp (k1=+rp) and j=64-rp (k1=-rp);
//   rp==0 covers j=0 (running sum) and j=32 (k1=-32, base angle 32h).
__global__ __launch_bounds__(256) void k_s1s2(const float* __restrict__ x, int trans) {
    __shared__ ull bufu[3104];            // A-buffers / Tr,Ti planes (aliased)
    __shared__ float str[256], sti[256];
    __shared__ float sx128[64];
    float* buf = (float*)bufu;
    float* xe  = buf;                     // [32 w'][65]
    float* xo  = buf + 2080;
    float* sCc = buf + 4160;              // [32 kk][32 k2]
    float* sCs = buf + 5184;
    ull* sTr = bufu;                      // [64 h][18 ull]
    ull* sTi = bufu + 1152;

    int t  = threadIdx.x;
    int ch = blockIdx.x;
    const float* xc = x + (size_t)ch * 65536;
    str[t] = g_twr[t];
    sti[t] = g_twi[t];

    int rp = t >> 3;                      // 0..31
    int kg = t & 7;                       // k2 group of 4 (2 ull)
    int m  = rp ? rp : 32;                // twiddle base multiplier
    ull Aq[2], Bq[2], Cq[2], Dq[2], SrA[2], SiA[2];
#pragma unroll
    for (int q = 0; q < 2; q++) { Aq[q]=0ull; Bq[q]=0ull; Cq[q]=0ull; Dq[q]=0ull; SrA[q]=0ull; SiA[q]=0ull; }

    for (int hc = 0; hc < 4; hc++) {
        ull Tr0[2], Ti0[2], Tr1[2], Ti1[2];
#pragma unroll
        for (int q = 0; q < 2; q++) { Tr0[q]=0ull; Ti0[q]=0ull; Tr1[q]=0ull; Ti1[q]=0ull; }

        for (int kc = 0; kc < 4; kc++) {
            __syncthreads();
            ((float4*)sCc)[t] = ((const float4*)(g_Cc + kc * 1024))[t];
            ((float4*)sCs)[t] = ((const float4*)(g_Cs + kc * 1024))[t];
#pragma unroll
            for (int q = 0; q < 8; q++) {
                int flat = q * 256 + t;
                int wl, row;
                if (!trans) { wl = flat & 31; row = flat >> 5; }
                else        { row = flat & 63; wl = flat >> 6; }
                int wp = kc * 32 + wl;
                float xv, xm;
                if (!trans) {
                    xv = xc[(hc * 64 + row) * 256 + wp];
                    xm = (wp == 0) ? 0.f : xc[(hc * 64 + row) * 256 + 256 - wp];
                } else {
                    xv = xc[wp * 256 + hc * 64 + row];
                    xm = (wp == 0) ? 0.f : xc[(256 - wp) * 256 + hc * 64 + row];
                }
                xe[wl * 65 + row] = (wp == 0) ? xv : xv + xm;
                xo[wl * 65 + row] = (wp == 0) ? 0.f : xv - xm;
                if (wp == 0)
                    sx128[row] = (!trans) ? xc[(hc * 64 + row) * 256 + 128]
                                          : xc[128 * 256 + hc * 64 + row];
            }
            __syncthreads();
#pragma unroll 4
            for (int kk = 0; kk < 32; kk++) {
                float a0e = xe[kk * 65 + rp];
                float a1e = xe[kk * 65 + rp + 32];
                float a0o = xo[kk * 65 + rp];
                float a1o = xo[kk * 65 + rp + 32];
                ull pa0e = pk2(a0e, a0e), pa1e = pk2(a1e, a1e);
                ull pa0o = pk2(a0o, a0o), pa1o = pk2(a1o, a1o);
                ulonglong2 c01 = *(const ulonglong2*)(sCc + kk * 32 + kg * 4);
                ulonglong2 s01 = *(const ulonglong2*)(sCs + kk * 32 + kg * 4);
                Tr0[0] = ffma2(pa0e, c01.x, Tr0[0]); Tr0[1] = ffma2(pa0e, c01.y, Tr0[1]);
                Tr1[0] = ffma2(pa1e, c01.x, Tr1[0]); Tr1[1] = ffma2(pa1e, c01.y, Tr1[1]);
                Ti0[0] = ffma2(pa0o, s01.x, Ti0[0]); Ti0[1] = ffma2(pa0o, s01.y, Ti0[1]);
                Ti1[0] = ffma2(pa1o, s01.x, Ti1[0]); Ti1[1] = ffma2(pa1o, s01.y, Ti1[1]);
            }
        }
        {   // x[128] parity term (pairs are (even k2, odd k2))
            const ull PM = pk2(1.f, -1.f);
            ull px0 = pk2(sx128[rp], sx128[rp]);
            ull px1 = pk2(sx128[rp + 32], sx128[rp + 32]);
#pragma unroll
            for (int q = 0; q < 2; q++) {
                Tr0[q] = ffma2(px0, PM, Tr0[q]);
                Tr1[q] = ffma2(px1, PM, Tr1[q]);
            }
        }
        __syncthreads();
#pragma unroll
        for (int q = 0; q < 2; q++) {
            sTr[rp * 18 + kg * 2 + q]        = Tr0[q];
            sTi[rp * 18 + kg * 2 + q]        = Ti0[q];
            sTr[(rp + 32) * 18 + kg * 2 + q] = Tr1[q];
            sTi[(rp + 32) * 18 + kg * 2 + q] = Ti1[q];
        }
        __syncthreads();
        // Phase B: accumulate A,B',C',D at base angle m*h
#pragma unroll 2
        for (int hh = 0; hh < 64; hh++) {
            int h   = hc * 64 + hh;
            int idx = (m * h) & 255;
            float c = str[idx], s = sti[idx];
            ull cp = pk2(c, c), sp = pk2(s, s);
            ulonglong2 tr = *(const ulonglong2*)(sTr + hh * 18 + kg * 2);
            ulonglong2 ti = *(const ulonglong2*)(sTi + hh * 18 + kg * 2);
            Aq[0] = ffma2(tr.x, cp, Aq[0]); Cq[0] = ffma2(tr.x, sp, Cq[0]);
            Dq[0] = ffma2(ti.x, cp, Dq[0]); Bq[0] = ffma2(ti.x, sp, Bq[0]);
            Aq[1] = ffma2(tr.y, cp, Aq[1]); Cq[1] = ffma2(tr.y, sp, Cq[1]);
            Dq[1] = ffma2(ti.y, cp, Dq[1]); Bq[1] = ffma2(ti.y, sp, Bq[1]);
            if (rp == 0) {
                SrA[0] = add2(SrA[0], tr.x); SrA[1] = add2(SrA[1], tr.y);
                SiA[0] = add2(SiA[0], ti.x); SiA[1] = add2(SiA[1], ti.y);
            }
        }
    }
    // combine: XF(+k) = (A-B', D+C'); XF(-k) = (A+B', D-C'); rp==0: j0 = S, j32 = -32 slot
    {
        const ull M1 = pk2(-1.f, -1.f);
        float4* XF4 = (float4*)(g_XF + (size_t)ch * 4096);
        int jhi = rp ? (64 - rp) : 32;
#pragma unroll
        for (int q = 0; q < 2; q++) {
            ull rhi = add2(Aq[q], Bq[q]);
            ull ihi = ffma2(Cq[q], M1, Dq[q]);
            ull rlo = rp ? ffma2(Bq[q], M1, Aq[q]) : SrA[q];
            ull ilo = rp ? add2(Dq[q], Cq[q])      : SiA[q];
            float2 a = upk(rlo), b = upk(ilo);
            float2 cc = upk(rhi), d = upk(ihi);
            XF4[rp * 16 + kg * 2 + q]  = make_float4(a.x, b.x, a.y, b.y);
            XF4[jhi * 16 + kg * 2 + q] = make_float4(cc.x, d.x, cc.y, d.y);
        }
    }
}

// ---------------- stage 3: mode mix (FFMA2, k2-paired) ----------------------
__global__ __launch_bounds__(256) void k_s3(const float* __restrict__ wAr,
                                            const float* __restrict__ wAi,
                                            const float* __restrict__ wBr,
                                            const float* __restrict__ wBi) {
    __shared__ ull sp[4096];              // sxr 2048 | sxi 2048 (32 KB)
    float* sxr = (float*)sp;
    float* sxi = (float*)(sp + 2048);
    int t  = threadIdx.x;
    int j  = blockIdx.x >> 3;
    int ot = blockIdx.x & 7;
    int o  = ot * 8 + (t >> 5);
    int lane = t & 31;
    int bh   = lane >> 4;
    int k2a  = (lane & 15) * 2;
    const float* wr; const float* wi; int jw;
    if (j < 32) { wr = wAr; wi = wAi; jw = j; }
    else        { wr = wBr; wi = wBi; jw = j - 32; }
    ull yrp[4], yip[4];
#pragma unroll
    for (int b = 0; b < 4; b++) { yrp[b] = 0ull; yip[b] = 0ull; }
    const float2* XF = (const float2*)g_XF;

    for (int ic = 0; ic < 4; ic++) {
        __syncthreads();
#pragma unroll
        for (int q = 0; q < 16; q++) {
            int flat = q * 256 + t;
            int kl = flat & 31;
            int ii = (flat >> 5) & 15;
            int b  = flat >> 9;
            float2 v = XF[((size_t)(b * 64 + ic * 16 + ii) * 64 + j) * 32 + kl];
            sxr[(b * 16 + ii) * 32 + kl] = v.x;
            sxi[(b * 16 + ii) * 32 + kl] = v.y;
        }
        __syncthreads();
#pragma unroll 4
        for (int ii = 0; ii < 16; ii++) {
            int i = ic * 16 + ii;
            size_t wb = (size_t)(i * 64 + o) * 1024 + jw * 32 + k2a;
            float2 wre2 = *(const float2*)(wr + wb);
            float2 wim2 = *(const float2*)(wi + wb);
            ull wrp  = pk2(wre2.x, wre2.y);
            ull wip  = pk2(wim2.x, wim2.y);
            ull nwip = pk2(-wim2.x, -wim2.y);
#pragma unroll
            for (int bb = 0; bb < 4; bb++) {
                int b = bh * 4 + bb;
                ull xrp = *(const ull*)(sxr + (b * 16 + ii) * 32 + k2a);
                ull xip = *(const ull*)(sxi + (b * 16 + ii) * 32 + k2a);
                yrp[bb] = ffma2(xrp, wrp, yrp[bb]);  yrp[bb] = ffma2(xip, nwip, yrp[bb]);
                yip[bb] = ffma2(xrp, wip, yip[bb]);  yip[bb] = ffma2(xip, wrp,  yip[bb]);
            }
        }
    }
#pragma unroll
    for (int bb = 0; bb < 4; bb++) {
        int b = bh * 4 + bb;
        float2 r = upk(yrp[bb]), im = upk(yip[bb]);
        *(float4*)(g_Y + (((size_t)(b * 64 + o) * 64 + j) * 32 + k2a) * 2) =
            make_float4(r.x, im.x, r.y, im.y);
    }
}

// ---------------- fused stage 4+5 (256 threads, +-j paired Phase A) ---------
// block = (ch, g0 in {0,64}); covers h rows [g0,g0+64) and [g0+128,g0+192).
__global__ __launch_bounds__(256) void k_s4s5(float* __restrict__ out) {
    __shared__ float zsA[64 * 68];
    __shared__ float zsB[64 * 68];
    __shared__ ull reg2u[2304];           // sY planes (E/O transformed), later F staging
    __shared__ float str[256], sti[256];
    float* reg2 = (float*)reg2u;
    int t  = threadIdx.x;
    int ch = blockIdx.x >> 1;
    int g0 = (blockIdx.x & 1) << 6;
    str[t] = g_twr[t];
    sti[t] = g_twi[t];

    float* pYr = reg2;                    // [j][36]
    float* pYi = reg2 + 2304;
    {   // stage Y -> deinterleaved planes
        const float2* Yg = (const float2*)(g_Y + (size_t)ch * 4096);
#pragma unroll
        for (int q = 0; q < 8; q++) {
            int flat = q * 256 + t;
            int jj = flat >> 5, kl = flat & 31;
            float2 v = Yg[flat];
            pYr[jj * 36 + kl] = v.x;
            pYi[jj * 36 + kl] = v.y;
        }
    }
    __syncthreads();
    {   // E/O transform in place: row a <- Y[a]+Y[64-a], row 64-a <- Y[a]-Y[64-a]
#pragma unroll
        for (int q = 0; q < 4; q++) {
            int flat = q * 256 + t;
            if (flat < 992) {
                int a = (flat >> 5) + 1;
                int col = flat & 31;
                float ya = pYr[a * 36 + col], yb = pYr[(64 - a) * 36 + col];
                pYr[a * 36 + col] = ya + yb;
                pYr[(64 - a) * 36 + col] = ya - yb;
                float za = pYi[a * 36 + col], zb = pYi[(64 - a) * 36 + col];
                pYi[a * 36 + col] = za + zb;
                pYi[(64 - a) * 36 + col] = za - zb;
            }
        }
    }
    __syncthreads();
    ull* sYr = reg2u;
    ull* sYi = reg2u + 1152;

    int hp = t >> 3;                      // 0..31
    int kg = t & 7;                       // k2 group of 4 (2 ull)
    int hA = g0 + hp;
    ull ze0r[2], ze0i[2], zo0r[2], zo0i[2];   // h = hA
    ull ze1r[2], ze1i[2], zo1r[2], zo1i[2];   // h = hA+32
#pragma unroll
    for (int q = 0; q < 2; q++) {
        ze0r[q]=0ull; ze0i[q]=0ull; zo0r[q]=0ull; zo0i[q]=0ull;
        ze1r[q]=0ull; ze1i[q]=0ull; zo1r[q]=0ull; zo1i[q]=0ull;
    }

#define PBODY(A, R0, I0, R1, I1) { \
    int ia = ((A) * hA) & 255; \
    int ib = (ia + (A) * 32) & 255; \
    float c0 = str[ia], t0 = sti[ia]; \
    float c1 = str[ib], t1 = sti[ib]; \
    ull c0p = pk2(c0, c0), t0p = pk2(t0, t0), n0p = pk2(-t0, -t0); \
    ull c1p = pk2(c1, c1), t1p = pk2(t1, t1), n1p = pk2(-t1, -t1); \
    ulonglong2 er  = *(const ulonglong2*)(sYr + (A) * 18 + kg * 2); \
    ulonglong2 ei  = *(const ulonglong2*)(sYi + (A) * 18 + kg * 2); \
    ulonglong2 orr = *(const ulonglong2*)(sYr + (64 - (A)) * 18 + kg * 2); \
    ulonglong2 oii = *(const ulonglong2*)(sYi + (64 - (A)) * 18 + kg * 2); \
    R0[0] = ffma2(er.x, c0p, R0[0]);  R0[0] = ffma2(oii.x, t0p, R0[0]); \
    I0[0] = ffma2(ei.x, c0p, I0[0]);  I0[0] = ffma2(orr.x, n0p, I0[0]); \
    R0[1] = ffma2(er.y, c0p, R0[1]);  R0[1] = ffma2(oii.y, t0p, R0[1]); \
    I0[1] = ffma2(ei.y, c0p, I0[1]);  I0[1] = ffma2(orr.y, n0p, I0[1]); \
    R1[0] = ffma2(er.x, c1p, R1[0]);  R1[0] = ffma2(oii.x, t1p, R1[0]); \
    I1[0] = ffma2(ei.x, c1p, I1[0]);  I1[0] = ffma2(orr.x, n1p, I1[0]); \
    R1[1] = ffma2(er.y, c1p, R1[1]);  R1[1] = ffma2(oii.y, t1p, R1[1]); \
    I1[1] = ffma2(ei.y, c1p, I1[1]);  I1[1] = ffma2(orr.y, n1p, I1[1]); }

#pragma unroll 3
    for (int ap = 0; ap < 15; ap++) {
        PBODY(2 * ap + 1, zo0r, zo0i, zo1r, zo1i)
        PBODY(2 * ap + 2, ze0r, ze0i, ze1r, ze1i)
    }
    PBODY(31, zo0r, zo0i, zo1r, zo1i)
#undef PBODY

    {   // j=0 (k1=0, even): constant contribution Y0 to both h regs
        ulonglong2 y0r = *(const ulonglong2*)(sYr + kg * 2);
        ulonglong2 y0i = *(const ulonglong2*)(sYi + kg * 2);
        ze0r[0] = add2(ze0r[0], y0r.x); ze0r[1] = add2(ze0r[1], y0r.y);
        ze0i[0] = add2(ze0i[0], y0i.x); ze0i[1] = add2(ze0i[1], y0i.y);
        ze1r[0] = add2(ze1r[0], y0r.x); ze1r[1] = add2(ze1r[1], y0r.y);
        ze1i[0] = add2(ze1i[0], y0i.x); ze1i[1] = add2(ze1i[1], y0i.y);
    }
    {   // j=32 (k1=-32, even): e^{-i32h} -- same angle for hA and hA+32
        int i32 = (32 * hA) & 255;
        float c = str[i32], tv = sti[i32];
        ull cp = pk2(c, c), tp = pk2(tv, tv), np = pk2(-tv, -tv);
        ulonglong2 y2r = *(const ulonglong2*)(sYr + 32 * 18 + kg * 2);
        ulonglong2 y2i = *(const ulonglong2*)(sYi + 32 * 18 + kg * 2);
#pragma unroll
        for (int q = 0; q < 2; q++) {
            ull r2v = q ? y2r.y : y2r.x;
            ull i2v = q ? y2i.y : y2i.x;
            ze0r[q] = ffma2(r2v, cp, ze0r[q]);  ze0r[q] = ffma2(i2v, np, ze0r[q]);
            ze0i[q] = ffma2(i2v, cp, ze0i[q]);  ze0i[q] = ffma2(r2v, tp, ze0i[q]);
            ze1r[q] = ffma2(r2v, cp, ze1r[q]);  ze1r[q] = ffma2(i2v, np, ze1r[q]);
            ze1i[q] = ffma2(i2v, cp, ze1i[q]);  ze1i[q] = ffma2(r2v, tp, ze1i[q]);
        }
    }

    // combine parity partials -> both h tiles
    {
        const ull M1 = pk2(-1.f, -1.f);
#pragma unroll
        for (int q = 0; q < 2; q++) {
            int c2 = 2 * (kg * 4 + 2 * q);
            float2 ra, ia, rb, ib;
            ra = upk(add2(ze0r[q], zo0r[q]));  ia = upk(add2(ze0i[q], zo0i[q]));
            rb = upk(ffma2(zo0r[q], M1, ze0r[q]));  ib = upk(ffma2(zo0i[q], M1, ze0i[q]));
            zsA[c2 * 68 + hp]       = ra.x; zsA[(c2 + 1) * 68 + hp] = ia.x;
            zsA[(c2 + 2) * 68 + hp] = ra.y; zsA[(c2 + 3) * 68 + hp] = ia.y;
            zsB[c2 * 68 + hp]       = rb.x; zsB[(c2 + 1) * 68 + hp] = ib.x;
            zsB[(c2 + 2) * 68 + hp] = rb.y; zsB[(c2 + 3) * 68 + hp] = ib.y;
            ra = upk(add2(ze1r[q], zo1r[q]));  ia = upk(add2(ze1i[q], zo1i[q]));
            rb = upk(ffma2(zo1r[q], M1, ze1r[q]));  ib = upk(ffma2(zo1i[q], M1, ze1i[q]));
            zsA[c2 * 68 + hp + 32]       = ra.x; zsA[(c2 + 1) * 68 + hp + 32] = ia.x;
            zsA[(c2 + 2) * 68 + hp + 32] = ra.y; zsA[(c2 + 3) * 68 + hp + 32] = ia.y;
            zsB[c2 * 68 + hp + 32]       = rb.x; zsB[(c2 + 1) * 68 + hp + 32] = ib.x;
            zsB[(c2 + 2) * 68 + hp + 32] = rb.y; zsB[(c2 + 3) * 68 + hp + 32] = ib.y;
        }
    }
    __syncthreads();

    // w=128 columns for both tiles
    if (t < 128) {
        int tile = t >> 6;
        int row  = t & 63;
        const float* zz = tile ? zsB : zsA;
        float s = zz[row];
#pragma unroll
        for (int k2 = 1; k2 < 32; k2++)
            s += ((k2 & 1) ? -2.f : 2.f) * zz[2 * k2 * 68 + row];
        out[((size_t)ch * 256 + g0 + tile * 128 + row) * 256 + 128] = s * (1.f / 65536.f);
    }

    // Phase B: folded inverse-w, BOTH tiles per k2 step (shared F loads).
    // thread = (hg = t>>4 -> 4 h rows, wg = t&15 -> 2 w' cols); wt chunks of 32 w'.
    int hg = t >> 4;
    int wg = t & 15;
    const float4* FcG = (const float4*)g_Fc;
    const float4* FsG = (const float4*)g_Fs;
    const ull M1 = pk2(-1.f, -1.f);
    for (int wt = 0; wt < 4; wt++) {
        __syncthreads();
        {   // stage Fc/Fs chunk: 32 k2 x 32 w' each (one float4 per thread)
            int k2s = t >> 3, u = t & 7;
            ((float4*)reg2)[k2s * 8 + u]       = FcG[k2s * 32 + wt * 8 + u];
            ((float4*)reg2)[256 + k2s * 8 + u] = FsG[k2s * 32 + wt * 8 + u];
        }
        __syncthreads();
        ull PA[4], QA[4], PB[4], QB[4];
#pragma unroll
        for (int q = 0; q < 4; q++) { PA[q]=0ull; QA[q]=0ull; PB[q]=0ull; QB[q]=0ull; }
#pragma unroll 4
        for (int k2 = 0; k2 < 32; k2++) {
            float4 aA = *(const float4*)(zsA + (2 * k2) * 68 + hg * 4);
            float4 bA = *(const float4*)(zsA + (2 * k2 + 1) * 68 + hg * 4);
            float4 aB = *(const float4*)(zsB + (2 * k2) * 68 + hg * 4);
            float4 bB = *(const float4*)(zsB + (2 * k2 + 1) * 68 + hg * 4);
            ull f = *(const ull*)(reg2 + k2 * 32 + wg * 2);
            ull g = *(const ull*)(reg2 + 1024 + k2 * 32 + wg * 2);
            ull pr, pi;
#define BROW2(R, AVA, BVA, AVB, BVB) \
            pr = pk2(AVA, AVA); pi = pk2(BVA, BVA); \
            PA[R] = ffma2(pr, f, PA[R]); QA[R] = ffma2(pi, g, QA[R]); \
            pr = pk2(AVB, AVB); pi = pk2(BVB, BVB); \
            PB[R] = ffma2(pr, f, PB[R]); QB[R] = ffma2(pi, g, QB[R]);
            BROW2(0, aA.x, bA.x, aB.x, bB.x)
            BROW2(1, aA.y, bA.y, aB.y, bB.y)
            BROW2(2, aA.z, bA.z, aB.z, bB.z)
            BROW2(3, aA.w, bA.w, aB.w, bB.w)
#undef BROW2
        }
        int wbase = wt * 32 + wg * 2;
#pragma unroll
        for (int r = 0; r < 4; r++) {
            int hloc = hg * 4 + r;
            {   // tile A (h rows g0..g0+63)
                float* orow = out + ((size_t)ch * 256 + g0 + hloc) * 256;
                ull Av = add2(PA[r], QA[r]);
                ull Bv = ffma2(QA[r], M1, PA[r]);
                float2 fa = upk(Av), fb = upk(Bv);
                *(float2*)(orow + wbase) = fa;
#pragma unroll
                for (int i = 0; i < 2; i++) {
                    int wv = wbase + i;
                    if (wv) orow[256 - wv] = i ? fb.y : fb.x;
                }
            }
            {   // tile B (h rows g0+128..g0+191)
                float* orow = out + ((size_t)ch * 256 + g0 + 128 + hloc) * 256;
                ull Av = add2(PB[r], QB[r]);
                ull Bv = ffma2(QB[r], M1, PB[r]);
                float2 fa = upk(Av), fb = upk(Bv);
                *(float2*)(orow + wbase) = fa;
#pragma unroll
                for (int i = 0; i < 2; i++) {
                    int wv = wbase + i;
                    if (wv) orow[256 - wv] = i ? fb.y : fb.x;
                }
            }
        }
    }
}

// ---------------------------------------------------------------------------
extern "C" void kernel_launch(void* const* d_in, const int* in_sizes, int n_in,
                              void* d_out, int out_size) {
    const float* x   = (const float*)d_in[0];
    const float* w1r = (const float*)d_in[1];
    const float* w1i = (const float*)d_in[2];
    const float* w2r = (const float*)d_in[3];
    const float* w2i = (const float*)d_in[4];
    const float* w3r = (const float*)d_in[5];
    const float* w3i = (const float*)d_in[6];
    const float* w4r = (const float*)d_in[7];
    const float* w4i = (const float*)d_in[8];
    float* out = (float*)d_out;

    k_init<<<34, 256>>>();

    // ---- branch x ----
    k_s1s2<<<512, 256>>>(x, 0);
    k_s3<<<512, 256>>>(w1r, w1i, w2r, w2i);
    k_s4s5<<<1024, 256>>>(out);

    // ---- branch x^T ----
    k_s1s2<<<512, 256>>>(x, 1);
    k_s3<<<512, 256>>>(w3r, w3i, w4r, w4i);
    k_s4s5<<<1024, 256>>>(out + (size_t)NCH * 65536);
}

// round 15
// speedup vs baseline: 1.4674x; 1.0068x over previous
#include <cuda_runtime.h>

// ---------------------------------------------------------------------------
// SpectralConv2d (FNO). B=8, C=64, H=W=256, M1=M2=32. Two branches.
// v10: v7 + s4s5 Phase-B tile merge (shared F twiddle loads across both
// h-tiles; 2 w'/thread x 4 wt chunks keeps registers flat).
// ---------------------------------------------------------------------------

namespace {
constexpr int NCH = 512;           // B*C
}

typedef unsigned long long ull;

__device__ __forceinline__ ull pk2(float lo, float hi) {
    ull r; asm("mov.b64 %0, {%1,%2};" : "=l"(r) : "f"(lo), "f"(hi)); return r;
}
__device__ __forceinline__ ull ffma2(ull a, ull b, ull c) {
    ull d; asm("fma.rn.f32x2 %0, %1, %2, %3;" : "=l"(d) : "l"(a), "l"(b), "l"(c)); return d;
}
__device__ __forceinline__ ull add2(ull a, ull b) {
    ull d; asm("add.rn.f32x2 %0, %1, %2;" : "=l"(d) : "l"(a), "l"(b)); return d;
}
__device__ __forceinline__ float2 upk(ull v) {
    float2 r; asm("mov.b64 {%0,%1}, %2;" : "=f"(r.x), "=f"(r.y) : "l"(v)); return r;
}

__device__ float g_twr[256];
__device__ float g_twi[256];
__device__ float g_Cc[128 * 32];             // cos(2pi k2 w'/256) [w'][k2]
__device__ float g_Cs[128 * 32];             // -sin               [w'][k2]
__device__ float g_Fc[32 * 128];             // sc*(k2?2cos:1)     [k2][w']
__device__ float g_Fs[32 * 128];             // k2? -2sc*sin : 0   [k2][w']
__device__ float g_XF[NCH * 64 * 32 * 2];
__device__ float g_Y [NCH * 64 * 32 * 2];

// ---------------- init ------------------------------------------------------
__global__ void k_init() {
    int idx = blockIdx.x * 256 + threadIdx.x;
    const float sc = 1.0f / 65536.0f;
    if (idx < 256) {
        double s, c;
        sincospi(-2.0 * (double)idx / 256.0, &s, &c);
        g_twr[idx] = (float)c;
        g_twi[idx] = (float)s;
    } else if (idx < 256 + 4096) {
        int j = idx - 256;
        int wp = j >> 5, k2 = j & 31;
        int ang = (k2 * wp) & 255;
        double s, c;
        sincospi(-2.0 * (double)ang / 256.0, &s, &c);
        g_Cc[wp * 32 + k2] = (float)c;
        g_Cs[wp * 32 + k2] = (float)s;
    } else if (idx < 256 + 8192) {
        int j = idx - 4352;
        int k2 = j >> 7, wp = j & 127;
        int ang = (k2 * wp) & 255;
        double s, c;
        sincospi(-2.0 * (double)ang / 256.0, &s, &c);
        g_Fc[k2 * 128 + wp] = (k2 == 0) ? sc : 2.0f * sc * (float)c;
        g_Fs[k2 * 128 + wp] = (k2 == 0) ? 0.0f : 2.0f * sc * (float)s;
    }
}

// ---------------- fused stage 1+2 (256 threads) -----------------------------
// Phase A: thread = (row-pair rp in {rp,rp+32}, k2-group kg of 4).
// Phase B (+-k paired): thread rp covers j=rp (k1=+rp) and j=64-rp (k1=-rp);
//   rp==0 covers j=0 (running sum) and j=32 (k1=-32, base angle 32h).
__global__ __launch_bounds__(256) void k_s1s2(const float* __restrict__ x, int trans) {
    __shared__ ull bufu[3104];            // A-buffers / Tr,Ti planes (aliased)
    __shared__ float str[256], sti[256];
    __shared__ float sx128[64];
    float* buf = (float*)bufu;
    float* xe  = buf;                     // [32 w'][65]
    float* xo  = buf + 2080;
    float* sCc = buf + 4160;              // [32 kk][32 k2]
    float* sCs = buf + 5184;
    ull* sTr = bufu;                      // [64 h][18 ull]
    ull* sTi = bufu + 1152;

    int t  = threadIdx.x;
    int ch = blockIdx.x;
    const float* xc = x + (size_t)ch * 65536;
    str[t] = g_twr[t];
    sti[t] = g_twi[t];

    int rp = t >> 3;                      // 0..31
    int kg = t & 7;                       // k2 group of 4 (2 ull)
    int m  = rp ? rp : 32;                // twiddle base multiplier
    ull Aq[2], Bq[2], Cq[2], Dq[2], SrA[2], SiA[2];
#pragma unroll
    for (int q = 0; q < 2; q++) { Aq[q]=0ull; Bq[q]=0ull; Cq[q]=0ull; Dq[q]=0ull; SrA[q]=0ull; SiA[q]=0ull; }

    for (int hc = 0; hc < 4; hc++) {
        ull Tr0[2], Ti0[2], Tr1[2], Ti1[2];
#pragma unroll
        for (int q = 0; q < 2; q++) { Tr0[q]=0ull; Ti0[q]=0ull; Tr1[q]=0ull; Ti1[q]=0ull; }

        for (int kc = 0; kc < 4; kc++) {
            __syncthreads();
            ((float4*)sCc)[t] = ((const float4*)(g_Cc + kc * 1024))[t];
            ((float4*)sCs)[t] = ((const float4*)(g_Cs + kc * 1024))[t];
#pragma unroll
            for (int q = 0; q < 8; q++) {
                int flat = q * 256 + t;
                int wl, row;
                if (!trans) { wl = flat & 31; row = flat >> 5; }
                else        { row = flat & 63; wl = flat >> 6; }
                int wp = kc * 32 + wl;
                float xv, xm;
                if (!trans) {
                    xv = xc[(hc * 64 + row) * 256 + wp];
                    xm = (wp == 0) ? 0.f : xc[(hc * 64 + row) * 256 + 256 - wp];
                } else {
                    xv = xc[wp * 256 + hc * 64 + row];
                    xm = (wp == 0) ? 0.f : xc[(256 - wp) * 256 + hc * 64 + row];
                }
                xe[wl * 65 + row] = (wp == 0) ? xv : xv + xm;
                xo[wl * 65 + row] = (wp == 0) ? 0.f : xv - xm;
                if (wp == 0)
                    sx128[row] = (!trans) ? xc[(hc * 64 + row) * 256 + 128]
                                          : xc[128 * 256 + hc * 64 + row];
            }
            __syncthreads();
#pragma unroll 4
            for (int kk = 0; kk < 32; kk++) {
                float a0e = xe[kk * 65 + rp];
                float a1e = xe[kk * 65 + rp + 32];
                float a0o = xo[kk * 65 + rp];
                float a1o = xo[kk * 65 + rp + 32];
                ull pa0e = pk2(a0e, a0e), pa1e = pk2(a1e, a1e);
                ull pa0o = pk2(a0o, a0o), pa1o = pk2(a1o, a1o);
                ulonglong2 c01 = *(const ulonglong2*)(sCc + kk * 32 + kg * 4);
                ulonglong2 s01 = *(const ulonglong2*)(sCs + kk * 32 + kg * 4);
                Tr0[0] = ffma2(pa0e, c01.x, Tr0[0]); Tr0[1] = ffma2(pa0e, c01.y, Tr0[1]);
                Tr1[0] = ffma2(pa1e, c01.x, Tr1[0]); Tr1[1] = ffma2(pa1e, c01.y, Tr1[1]);
                Ti0[0] = ffma2(pa0o, s01.x, Ti0[0]); Ti0[1] = ffma2(pa0o, s01.y, Ti0[1]);
                Ti1[0] = ffma2(pa1o, s01.x, Ti1[0]); Ti1[1] = ffma2(pa1o, s01.y, Ti1[1]);
            }
        }
        {   // x[128] parity term (pairs are (even k2, odd k2))
            const ull PM = pk2(1.f, -1.f);
            ull px0 = pk2(sx128[rp], sx128[rp]);
            ull px1 = pk2(sx128[rp + 32], sx128[rp + 32]);
#pragma unroll
            for (int q = 0; q < 2; q++) {
                Tr0[q] = ffma2(px0, PM, Tr0[q]);
                Tr1[q] = ffma2(px1, PM, Tr1[q]);
            }
        }
        __syncthreads();
#pragma unroll
        for (int q = 0; q < 2; q++) {
            sTr[rp * 18 + kg * 2 + q]        = Tr0[q];
            sTi[rp * 18 + kg * 2 + q]        = Ti0[q];
            sTr[(rp + 32) * 18 + kg * 2 + q] = Tr1[q];
            sTi[(rp + 32) * 18 + kg * 2 + q] = Ti1[q];
        }
        __syncthreads();
        // Phase B: accumulate A,B',C',D at base angle m*h
#pragma unroll 2
        for (int hh = 0; hh < 64; hh++) {
            int h   = hc * 64 + hh;
            int idx = (m * h) & 255;
            float c = str[idx], s = sti[idx];
            ull cp = pk2(c, c), sp = pk2(s, s);
            ulonglong2 tr = *(const ulonglong2*)(sTr + hh * 18 + kg * 2);
            ulonglong2 ti = *(const ulonglong2*)(sTi + hh * 18 + kg * 2);
            Aq[0] = ffma2(tr.x, cp, Aq[0]); Cq[0] = ffma2(tr.x, sp, Cq[0]);
            Dq[0] = ffma2(ti.x, cp, Dq[0]); Bq[0] = ffma2(ti.x, sp, Bq[0]);
            Aq[1] = ffma2(tr.y, cp, Aq[1]); Cq[1] = ffma2(tr.y, sp, Cq[1]);
            Dq[1] = ffma2(ti.y, cp, Dq[1]); Bq[1] = ffma2(ti.y, sp, Bq[1]);
            if (rp == 0) {
                SrA[0] = add2(SrA[0], tr.x); SrA[1] = add2(SrA[1], tr.y);
                SiA[0] = add2(SiA[0], ti.x); SiA[1] = add2(SiA[1], ti.y);
            }
        }
    }
    // combine: XF(+k) = (A-B', D+C'); XF(-k) = (A+B', D-C'); rp==0: j0 = S, j32 = -32 slot
    {
        const ull M1 = pk2(-1.f, -1.f);
        float4* XF4 = (float4*)(g_XF + (size_t)ch * 4096);
        int jhi = rp ? (64 - rp) : 32;
#pragma unroll
        for (int q = 0; q < 2; q++) {
            ull rhi = add2(Aq[q], Bq[q]);
            ull ihi = ffma2(Cq[q], M1, Dq[q]);
            ull rlo = rp ? ffma2(Bq[q], M1, Aq[q]) : SrA[q];
            ull ilo = rp ? add2(Dq[q], Cq[q])      : SiA[q];
            float2 a = upk(rlo), b = upk(ilo);
            float2 cc = upk(rhi), d = upk(ihi);
            XF4[rp * 16 + kg * 2 + q]  = make_float4(a.x, b.x, a.y, b.y);
            XF4[jhi * 16 + kg * 2 + q] = make_float4(cc.x, d.x, cc.y, d.y);
        }
    }
}

// ---------------- stage 3: mode mix (FFMA2, k2-paired) ----------------------
__global__ __launch_bounds__(256) void k_s3(const float* __restrict__ wAr,
                                            const float* __restrict__ wAi,
                                            const float* __restrict__ wBr,
                                            const float* __restrict__ wBi) {
    __shared__ ull sp[4096];              // sxr 2048 | sxi 2048 (32 KB)
    float* sxr = (float*)sp;
    float* sxi = (float*)(sp + 2048);
    int t  = threadIdx.x;
    int j  = blockIdx.x >> 3;
    int ot = blockIdx.x & 7;
    int o  = ot * 8 + (t >> 5);
    int lane = t & 31;
    int bh   = lane >> 4;
    int k2a  = (lane & 15) * 2;
    const float* wr; const float* wi; int jw;
    if (j < 32) { wr = wAr; wi = wAi; jw = j; }
    else        { wr = wBr; wi = wBi; jw = j - 32; }
    ull yrp[4], yip[4];
#pragma unroll
    for (int b = 0; b < 4; b++) { yrp[b] = 0ull; yip[b] = 0ull; }
    const float2* XF = (const float2*)g_XF;

    for (int ic = 0; ic < 4; ic++) {
        __syncthreads();
#pragma unroll
        for (int q = 0; q < 16; q++) {
            int flat = q * 256 + t;
            int kl = flat & 31;
            int ii = (flat >> 5) & 15;
            int b  = flat >> 9;
            float2 v = XF[((size_t)(b * 64 + ic * 16 + ii) * 64 + j) * 32 + kl];
            sxr[(b * 16 + ii) * 32 + kl] = v.x;
            sxi[(b * 16 + ii) * 32 + kl] = v.y;
        }
        __syncthreads();
#pragma unroll 4
        for (int ii = 0; ii < 16; ii++) {
            int i = ic * 16 + ii;
            size_t wb = (size_t)(i * 64 + o) * 1024 + jw * 32 + k2a;
            float2 wre2 = *(const float2*)(wr + wb);
            float2 wim2 = *(const float2*)(wi + wb);
            ull wrp  = pk2(wre2.x, wre2.y);
            ull wip  = pk2(wim2.x, wim2.y);
            ull nwip = pk2(-wim2.x, -wim2.y);
#pragma unroll
            for (int bb = 0; bb < 4; bb++) {
                int b = bh * 4 + bb;
                ull xrp = *(const ull*)(sxr + (b * 16 + ii) * 32 + k2a);
                ull xip = *(const ull*)(sxi + (b * 16 + ii) * 32 + k2a);
                yrp[bb] = ffma2(xrp, wrp, yrp[bb]);  yrp[bb] = ffma2(xip, nwip, yrp[bb]);
                yip[bb] = ffma2(xrp, wip, yip[bb]);  yip[bb] = ffma2(xip, wrp,  yip[bb]);
            }
        }
    }
#pragma unroll
    for (int bb = 0; bb < 4; bb++) {
        int b = bh * 4 + bb;
        float2 r = upk(yrp[bb]), im = upk(yip[bb]);
        *(float4*)(g_Y + (((size_t)(b * 64 + o) * 64 + j) * 32 + k2a) * 2) =
            make_float4(r.x, im.x, r.y, im.y);
    }
}

// ---------------- fused stage 4+5 (256 threads, +-j paired Phase A) ---------
// block = (ch, g0 in {0,64}); covers h rows [g0,g0+64) and [g0+128,g0+192).
__global__ __launch_bounds__(256) void k_s4s5(float* __restrict__ out) {
    __shared__ float zsA[64 * 68];
    __shared__ float zsB[64 * 68];
    __shared__ ull reg2u[2304];           // sY planes (E/O transformed), later F staging
    __shared__ float str[256], sti[256];
    float* reg2 = (float*)reg2u;
    int t  = threadIdx.x;
    int ch = blockIdx.x >> 1;
    int g0 = (blockIdx.x & 1) << 6;
    str[t] = g_twr[t];
    sti[t] = g_twi[t];

    float* pYr = reg2;                    // [j][36]
    float* pYi = reg2 + 2304;
    {   // stage Y -> deinterleaved planes
        const float2* Yg = (const float2*)(g_Y + (size_t)ch * 4096);
#pragma unroll
        for (int q = 0; q < 8; q++) {
            int flat = q * 256 + t;
            int jj = flat >> 5, kl = flat & 31;
            float2 v = Yg[flat];
            pYr[jj * 36 + kl] = v.x;
            pYi[jj * 36 + kl] = v.y;
        }
    }
    __syncthreads();
    {   // E/O transform in place: row a <- Y[a]+Y[64-a], row 64-a <- Y[a]-Y[64-a]
#pragma unroll
        for (int q = 0; q < 4; q++) {
            int flat = q * 256 + t;
            if (flat < 992) {
                int a = (flat >> 5) + 1;
                int col = flat & 31;
                float ya = pYr[a * 36 + col], yb = pYr[(64 - a) * 36 + col];
                pYr[a * 36 + col] = ya + yb;
                pYr[(64 - a) * 36 + col] = ya - yb;
                float za = pYi[a * 36 + col], zb = pYi[(64 - a) * 36 + col];
                pYi[a * 36 + col] = za + zb;
                pYi[(64 - a) * 36 + col] = za - zb;
            }
        }
    }
    __syncthreads();
    ull* sYr = reg2u;
    ull* sYi = reg2u + 1152;

    int hp = t >> 3;                      // 0..31
    int kg = t & 7;                       // k2 group of 4 (2 ull)
    int hA = g0 + hp;
    ull ze0r[2], ze0i[2], zo0r[2], zo0i[2];   // h = hA
    ull ze1r[2], ze1i[2], zo1r[2], zo1i[2];   // h = hA+32
#pragma unroll
    for (int q = 0; q < 2; q++) {
        ze0r[q]=0ull; ze0i[q]=0ull; zo0r[q]=0ull; zo0i[q]=0ull;
        ze1r[q]=0ull; ze1i[q]=0ull; zo1r[q]=0ull; zo1i[q]=0ull;
    }

#define PBODY(A, R0, I0, R1, I1) { \
    int ia = ((A) * hA) & 255; \
    int ib = (ia + (A) * 32) & 255; \
    float c0 = str[ia], t0 = sti[ia]; \
    float c1 = str[ib], t1 = sti[ib]; \
    ull c0p = pk2(c0, c0), t0p = pk2(t0, t0), n0p = pk2(-t0, -t0); \
    ull c1p = pk2(c1, c1), t1p = pk2(t1, t1), n1p = pk2(-t1, -t1); \
    ulonglong2 er  = *(const ulonglong2*)(sYr + (A) * 18 + kg * 2); \
    ulonglong2 ei  = *(const ulonglong2*)(sYi + (A) * 18 + kg * 2); \
    ulonglong2 orr = *(const ulonglong2*)(sYr + (64 - (A)) * 18 + kg * 2); \
    ulonglong2 oii = *(const ulonglong2*)(sYi + (64 - (A)) * 18 + kg * 2); \
    R0[0] = ffma2(er.x, c0p, R0[0]);  R0[0] = ffma2(oii.x, t0p, R0[0]); \
    I0[0] = ffma2(ei.x, c0p, I0[0]);  I0[0] = ffma2(orr.x, n0p, I0[0]); \
    R0[1] = ffma2(er.y, c0p, R0[1]);  R0[1] = ffma2(oii.y, t0p, R0[1]); \
    I0[1] = ffma2(ei.y, c0p, I0[1]);  I0[1] = ffma2(orr.y, n0p, I0[1]); \
    R1[0] = ffma2(er.x, c1p, R1[0]);  R1[0] = ffma2(oii.x, t1p, R1[0]); \
    I1[0] = ffma2(ei.x, c1p, I1[0]);  I1[0] = ffma2(orr.x, n1p, I1[0]); \
    R1[1] = ffma2(er.y, c1p, R1[1]);  R1[1] = ffma2(oii.y, t1p, R1[1]); \
    I1[1] = ffma2(ei.y, c1p, I1[1]);  I1[1] = ffma2(orr.y, n1p, I1[1]); }

#pragma unroll 3
    for (int ap = 0; ap < 15; ap++) {
        PBODY(2 * ap + 1, zo0r, zo0i, zo1r, zo1i)
        PBODY(2 * ap + 2, ze0r, ze0i, ze1r, ze1i)
    }
    PBODY(31, zo0r, zo0i, zo1r, zo1i)
#undef PBODY

    {   // j=0 (k1=0, even): constant contribution Y0 to both h regs
        ulonglong2 y0r = *(const ulonglong2*)(sYr + kg * 2);
        ulonglong2 y0i = *(const ulonglong2*)(sYi + kg * 2);
        ze0r[0] = add2(ze0r[0], y0r.x); ze0r[1] = add2(ze0r[1], y0r.y);
        ze0i[0] = add2(ze0i[0], y0i.x); ze0i[1] = add2(ze0i[1], y0i.y);
        ze1r[0] = add2(ze1r[0], y0r.x); ze1r[1] = add2(ze1r[1], y0r.y);
        ze1i[0] = add2(ze1i[0], y0i.x); ze1i[1] = add2(ze1i[1], y0i.y);
    }
    {   // j=32 (k1=-32, even): e^{-i32h} -- same angle for hA and hA+32
        int i32 = (32 * hA) & 255;
        float c = str[i32], tv = sti[i32];
        ull cp = pk2(c, c), tp = pk2(tv, tv), np = pk2(-tv, -tv);
        ulonglong2 y2r = *(const ulonglong2*)(sYr + 32 * 18 + kg * 2);
        ulonglong2 y2i = *(const ulonglong2*)(sYi + 32 * 18 + kg * 2);
#pragma unroll
        for (int q = 0; q < 2; q++) {
            ull r2v = q ? y2r.y : y2r.x;
            ull i2v = q ? y2i.y : y2i.x;
            ze0r[q] = ffma2(r2v, cp, ze0r[q]);  ze0r[q] = ffma2(i2v, np, ze0r[q]);
            ze0i[q] = ffma2(i2v, cp, ze0i[q]);  ze0i[q] = ffma2(r2v, tp, ze0i[q]);
            ze1r[q] = ffma2(r2v, cp, ze1r[q]);  ze1r[q] = ffma2(i2v, np, ze1r[q]);
            ze1i[q] = ffma2(i2v, cp, ze1i[q]);  ze1i[q] = ffma2(r2v, tp, ze1i[q]);
        }
    }

    // combine parity partials -> both h tiles
    {
        const ull M1 = pk2(-1.f, -1.f);
#pragma unroll
        for (int q = 0; q < 2; q++) {
            int c2 = 2 * (kg * 4 + 2 * q);
            float2 ra, ia, rb, ib;
            ra = upk(add2(ze0r[q], zo0r[q]));  ia = upk(add2(ze0i[q], zo0i[q]));
            rb = upk(ffma2(zo0r[q], M1, ze0r[q]));  ib = upk(ffma2(zo0i[q], M1, ze0i[q]));
            zsA[c2 * 68 + hp]       = ra.x; zsA[(c2 + 1) * 68 + hp] = ia.x;
            zsA[(c2 + 2) * 68 + hp] = ra.y; zsA[(c2 + 3) * 68 + hp] = ia.y;
            zsB[c2 * 68 + hp]       = rb.x; zsB[(c2 + 1) * 68 + hp] = ib.x;
            zsB[(c2 + 2) * 68 + hp] = rb.y; zsB[(c2 + 3) * 68 + hp] = ib.y;
            ra = upk(add2(ze1r[q], zo1r[q]));  ia = upk(add2(ze1i[q], zo1i[q]));
            rb = upk(ffma2(zo1r[q], M1, ze1r[q]));  ib = upk(ffma2(zo1i[q], M1, ze1i[q]));
            zsA[c2 * 68 + hp + 32]       = ra.x; zsA[(c2 + 1) * 68 + hp + 32] = ia.x;
            zsA[(c2 + 2) * 68 + hp + 32] = ra.y; zsA[(c2 + 3) * 68 + hp + 32] = ia.y;
            zsB[c2 * 68 + hp + 32]       = rb.x; zsB[(c2 + 1) * 68 + hp + 32] = ib.x;
            zsB[(c2 + 2) * 68 + hp + 32] = rb.y; zsB[(c2 + 3) * 68 + hp + 32] = ib.y;
        }
    }
    __syncthreads();

    // w=128 columns for both tiles
    if (t < 128) {
        int tile = t >> 6;
        int row  = t & 63;
        const float* zz = tile ? zsB : zsA;
        float s = zz[row];
#pragma unroll
        for (int k2 = 1; k2 < 32; k2++)
            s += ((k2 & 1) ? -2.f : 2.f) * zz[2 * k2 * 68 + row];
        out[((size_t)ch * 256 + g0 + tile * 128 + row) * 256 + 128] = s * (1.f / 65536.f);
    }

    // Phase B: folded inverse-w, BOTH tiles per k2 step (shared F loads).
    // thread = (hg = t>>4 -> 4 h rows, wg = t&15 -> 2 w' cols); wt chunks of 32 w'.
    int hg = t >> 4;
    int wg = t & 15;
    const float4* FcG = (const float4*)g_Fc;
    const float4* FsG = (const float4*)g_Fs;
    const ull M1 = pk2(-1.f, -1.f);
    for (int wt = 0; wt < 4; wt++) {
        __syncthreads();
        {   // stage Fc/Fs chunk: 32 k2 x 32 w' each (one float4 per thread)
            int k2s = t >> 3, u = t & 7;
            ((float4*)reg2)[k2s * 8 + u]       = FcG[k2s * 32 + wt * 8 + u];
            ((float4*)reg2)[256 + k2s * 8 + u] = FsG[k2s * 32 + wt * 8 + u];
        }
        __syncthreads();
        ull PA[4], QA[4], PB[4], QB[4];
#pragma unroll
        for (int q = 0; q < 4; q++) { PA[q]=0ull; QA[q]=0ull; PB[q]=0ull; QB[q]=0ull; }
#pragma unroll 4
        for (int k2 = 0; k2 < 32; k2++) {
            float4 aA = *(const float4*)(zsA + (2 * k2) * 68 + hg * 4);
            float4 bA = *(const float4*)(zsA + (2 * k2 + 1) * 68 + hg * 4);
            float4 aB = *(const float4*)(zsB + (2 * k2) * 68 + hg * 4);
            float4 bB = *(const float4*)(zsB + (2 * k2 + 1) * 68 + hg * 4);
            ull f = *(const ull*)(reg2 + k2 * 32 + wg * 2);
            ull g = *(const ull*)(reg2 + 1024 + k2 * 32 + wg * 2);
            ull pr, pi;
#define BROW2(R, AVA, BVA, AVB, BVB) \
            pr = pk2(AVA, AVA); pi = pk2(BVA, BVA); \
            PA[R] = ffma2(pr, f, PA[R]); QA[R] = ffma2(pi, g, QA[R]); \
            pr = pk2(AVB, AVB); pi = pk2(BVB, BVB); \
            PB[R] = ffma2(pr, f, PB[R]); QB[R] = ffma2(pi, g, QB[R]);
            BROW2(0, aA.x, bA.x, aB.x, bB.x)
            BROW2(1, aA.y, bA.y, aB.y, bB.y)
            BROW2(2, aA.z, bA.z, aB.z, bB.z)
            BROW2(3, aA.w, bA.w, aB.w, bB.w)
#undef BROW2
        }
        int wbase = wt * 32 + wg * 2;
#pragma unroll
        for (int r = 0; r < 4; r++) {
            int hloc = hg * 4 + r;
            {   // tile A (h rows g0..g0+63)
                float* orow = out + ((size_t)ch * 256 + g0 + hloc) * 256;
                ull Av = add2(PA[r], QA[r]);
                ull Bv = ffma2(QA[r], M1, PA[r]);
                float2 fa = upk(Av), fb = upk(Bv);
                *(float2*)(orow + wbase) = fa;
#pragma unroll
                for (int i = 0; i < 2; i++) {
                    int wv = wbase + i;
                    if (wv) orow[256 - wv] = i ? fb.y : fb.x;
                }
            }
            {   // tile B (h rows g0+128..g0+191)
                float* orow = out + ((size_t)ch * 256 + g0 + 128 + hloc) * 256;
                ull Av = add2(PB[r], QB[r]);
                ull Bv = ffma2(QB[r], M1, PB[r]);
                float2 fa = upk(Av), fb = upk(Bv);
                *(float2*)(orow + wbase) = fa;
#pragma unroll
                for (int i = 0; i < 2; i++) {
                    int wv = wbase + i;
                    if (wv) orow[256 - wv] = i ? fb.y : fb.x;
                }
            }
        }
    }
}

// ---------------------------------------------------------------------------
extern "C" void kernel_launch(void* const* d_in, const int* in_sizes, int n_in,
                              void* d_out, int out_size) {
    const float* x   = (const float*)d_in[0];
    const float* w1r = (const float*)d_in[1];
    const float* w1i = (const float*)d_in[2];
    const float* w2r = (const float*)d_in[3];
    const float* w2i = (const float*)d_in[4];
    const float* w3r = (const float*)d_in[5];
    const float* w3i = (const float*)d_in[6];
    const float* w4r = (const float*)d_in[7];
    const float* w4i = (const float*)d_in[8];
    float* out = (float*)d_out;

    k_init<<<34, 256>>>();

    // ---- branch x ----
    k_s1s2<<<512, 256>>>(x, 0);
    k_s3<<<512, 256>>>(w1r, w1i, w2r, w2i);
    k_s4s5<<<1024, 256>>>(out);

    // ---- branch x^T ----
    k_s1s2<<<512, 256>>>(x, 1);
    k_s3<<<512, 256>>>(w3r, w3i, w4r, w4i);
    k_s4s5<<<1024, 256>>>(out + (size_t)NCH * 65536);
}

// round 16
// speedup vs baseline: 1.4850x; 1.0120x over previous
#include <cuda_runtime.h>

// ---------------------------------------------------------------------------
// SpectralConv2d (FNO). B=8, C=64, H=W=256, M1=M2=32. Two branches.
// v11: v10 + s4s5 occupancy (launch_bounds(256,4), negated O-real plane cuts
// regs/ALU) + s3 float4 weight loads with software prefetch.
// ---------------------------------------------------------------------------

namespace {
constexpr int NCH = 512;           // B*C
}

typedef unsigned long long ull;

__device__ __forceinline__ ull pk2(float lo, float hi) {
    ull r; asm("mov.b64 %0, {%1,%2};" : "=l"(r) : "f"(lo), "f"(hi)); return r;
}
__device__ __forceinline__ ull ffma2(ull a, ull b, ull c) {
    ull d; asm("fma.rn.f32x2 %0, %1, %2, %3;" : "=l"(d) : "l"(a), "l"(b), "l"(c)); return d;
}
__device__ __forceinline__ ull add2(ull a, ull b) {
    ull d; asm("add.rn.f32x2 %0, %1, %2;" : "=l"(d) : "l"(a), "l"(b)); return d;
}
__device__ __forceinline__ float2 upk(ull v) {
    float2 r; asm("mov.b64 {%0,%1}, %2;" : "=f"(r.x), "=f"(r.y) : "l"(v)); return r;
}

__device__ float g_twr[256];
__device__ float g_twi[256];
__device__ float g_Cc[128 * 32];             // cos(2pi k2 w'/256) [w'][k2]
__device__ float g_Cs[128 * 32];             // -sin               [w'][k2]
__device__ float g_Fc[32 * 128];             // sc*(k2?2cos:1)     [k2][w']
__device__ float g_Fs[32 * 128];             // k2? -2sc*sin : 0   [k2][w']
__device__ float g_XF[NCH * 64 * 32 * 2];
__device__ float g_Y [NCH * 64 * 32 * 2];

// ---------------- init ------------------------------------------------------
__global__ void k_init() {
    int idx = blockIdx.x * 256 + threadIdx.x;
    const float sc = 1.0f / 65536.0f;
    if (idx < 256) {
        double s, c;
        sincospi(-2.0 * (double)idx / 256.0, &s, &c);
        g_twr[idx] = (float)c;
        g_twi[idx] = (float)s;
    } else if (idx < 256 + 4096) {
        int j = idx - 256;
        int wp = j >> 5, k2 = j & 31;
        int ang = (k2 * wp) & 255;
        double s, c;
        sincospi(-2.0 * (double)ang / 256.0, &s, &c);
        g_Cc[wp * 32 + k2] = (float)c;
        g_Cs[wp * 32 + k2] = (float)s;
    } else if (idx < 256 + 8192) {
        int j = idx - 4352;
        int k2 = j >> 7, wp = j & 127;
        int ang = (k2 * wp) & 255;
        double s, c;
        sincospi(-2.0 * (double)ang / 256.0, &s, &c);
        g_Fc[k2 * 128 + wp] = (k2 == 0) ? sc : 2.0f * sc * (float)c;
        g_Fs[k2 * 128 + wp] = (k2 == 0) ? 0.0f : 2.0f * sc * (float)s;
    }
}

// ---------------- fused stage 1+2 (256 threads) -----------------------------
__global__ __launch_bounds__(256) void k_s1s2(const float* __restrict__ x, int trans) {
    __shared__ ull bufu[3104];            // A-buffers / Tr,Ti planes (aliased)
    __shared__ float str[256], sti[256];
    __shared__ float sx128[64];
    float* buf = (float*)bufu;
    float* xe  = buf;                     // [32 w'][65]
    float* xo  = buf + 2080;
    float* sCc = buf + 4160;              // [32 kk][32 k2]
    float* sCs = buf + 5184;
    ull* sTr = bufu;                      // [64 h][18 ull]
    ull* sTi = bufu + 1152;

    int t  = threadIdx.x;
    int ch = blockIdx.x;
    const float* xc = x + (size_t)ch * 65536;
    str[t] = g_twr[t];
    sti[t] = g_twi[t];

    int rp = t >> 3;                      // 0..31
    int kg = t & 7;                       // k2 group of 4 (2 ull)
    int m  = rp ? rp : 32;                // twiddle base multiplier
    ull Aq[2], Bq[2], Cq[2], Dq[2], SrA[2], SiA[2];
#pragma unroll
    for (int q = 0; q < 2; q++) { Aq[q]=0ull; Bq[q]=0ull; Cq[q]=0ull; Dq[q]=0ull; SrA[q]=0ull; SiA[q]=0ull; }

    for (int hc = 0; hc < 4; hc++) {
        ull Tr0[2], Ti0[2], Tr1[2], Ti1[2];
#pragma unroll
        for (int q = 0; q < 2; q++) { Tr0[q]=0ull; Ti0[q]=0ull; Tr1[q]=0ull; Ti1[q]=0ull; }

        for (int kc = 0; kc < 4; kc++) {
            __syncthreads();
            ((float4*)sCc)[t] = ((const float4*)(g_Cc + kc * 1024))[t];
            ((float4*)sCs)[t] = ((const float4*)(g_Cs + kc * 1024))[t];
#pragma unroll
            for (int q = 0; q < 8; q++) {
                int flat = q * 256 + t;
                int wl, row;
                if (!trans) { wl = flat & 31; row = flat >> 5; }
                else        { row = flat & 63; wl = flat >> 6; }
                int wp = kc * 32 + wl;
                float xv, xm;
                if (!trans) {
                    xv = xc[(hc * 64 + row) * 256 + wp];
                    xm = (wp == 0) ? 0.f : xc[(hc * 64 + row) * 256 + 256 - wp];
                } else {
                    xv = xc[wp * 256 + hc * 64 + row];
                    xm = (wp == 0) ? 0.f : xc[(256 - wp) * 256 + hc * 64 + row];
                }
                xe[wl * 65 + row] = (wp == 0) ? xv : xv + xm;
                xo[wl * 65 + row] = (wp == 0) ? 0.f : xv - xm;
                if (wp == 0)
                    sx128[row] = (!trans) ? xc[(hc * 64 + row) * 256 + 128]
                                          : xc[128 * 256 + hc * 64 + row];
            }
            __syncthreads();
#pragma unroll 4
            for (int kk = 0; kk < 32; kk++) {
                float a0e = xe[kk * 65 + rp];
                float a1e = xe[kk * 65 + rp + 32];
                float a0o = xo[kk * 65 + rp];
                float a1o = xo[kk * 65 + rp + 32];
                ull pa0e = pk2(a0e, a0e), pa1e = pk2(a1e, a1e);
                ull pa0o = pk2(a0o, a0o), pa1o = pk2(a1o, a1o);
                ulonglong2 c01 = *(const ulonglong2*)(sCc + kk * 32 + kg * 4);
                ulonglong2 s01 = *(const ulonglong2*)(sCs + kk * 32 + kg * 4);
                Tr0[0] = ffma2(pa0e, c01.x, Tr0[0]); Tr0[1] = ffma2(pa0e, c01.y, Tr0[1]);
                Tr1[0] = ffma2(pa1e, c01.x, Tr1[0]); Tr1[1] = ffma2(pa1e, c01.y, Tr1[1]);
                Ti0[0] = ffma2(pa0o, s01.x, Ti0[0]); Ti0[1] = ffma2(pa0o, s01.y, Ti0[1]);
                Ti1[0] = ffma2(pa1o, s01.x, Ti1[0]); Ti1[1] = ffma2(pa1o, s01.y, Ti1[1]);
            }
        }
        {   // x[128] parity term (pairs are (even k2, odd k2))
            const ull PM = pk2(1.f, -1.f);
            ull px0 = pk2(sx128[rp], sx128[rp]);
            ull px1 = pk2(sx128[rp + 32], sx128[rp + 32]);
#pragma unroll
            for (int q = 0; q < 2; q++) {
                Tr0[q] = ffma2(px0, PM, Tr0[q]);
                Tr1[q] = ffma2(px1, PM, Tr1[q]);
            }
        }
        __syncthreads();
#pragma unroll
        for (int q = 0; q < 2; q++) {
            sTr[rp * 18 + kg * 2 + q]        = Tr0[q];
            sTi[rp * 18 + kg * 2 + q]        = Ti0[q];
            sTr[(rp + 32) * 18 + kg * 2 + q] = Tr1[q];
            sTi[(rp + 32) * 18 + kg * 2 + q] = Ti1[q];
        }
        __syncthreads();
        // Phase B: accumulate A,B',C',D at base angle m*h
#pragma unroll 2
        for (int hh = 0; hh < 64; hh++) {
            int h   = hc * 64 + hh;
            int idx = (m * h) & 255;
            float c = str[idx], s = sti[idx];
            ull cp = pk2(c, c), sp = pk2(s, s);
            ulonglong2 tr = *(const ulonglong2*)(sTr + hh * 18 + kg * 2);
            ulonglong2 ti = *(const ulonglong2*)(sTi + hh * 18 + kg * 2);
            Aq[0] = ffma2(tr.x, cp, Aq[0]); Cq[0] = ffma2(tr.x, sp, Cq[0]);
            Dq[0] = ffma2(ti.x, cp, Dq[0]); Bq[0] = ffma2(ti.x, sp, Bq[0]);
            Aq[1] = ffma2(tr.y, cp, Aq[1]); Cq[1] = ffma2(tr.y, sp, Cq[1]);
            Dq[1] = ffma2(ti.y, cp, Dq[1]); Bq[1] = ffma2(ti.y, sp, Bq[1]);
            if (rp == 0) {
                SrA[0] = add2(SrA[0], tr.x); SrA[1] = add2(SrA[1], tr.y);
                SiA[0] = add2(SiA[0], ti.x); SiA[1] = add2(SiA[1], ti.y);
            }
        }
    }
    // combine: XF(+k) = (A-B', D+C'); XF(-k) = (A+B', D-C'); rp==0: j0 = S, j32 = -32 slot
    {
        const ull M1 = pk2(-1.f, -1.f);
        float4* XF4 = (float4*)(g_XF + (size_t)ch * 4096);
        int jhi = rp ? (64 - rp) : 32;
#pragma unroll
        for (int q = 0; q < 2; q++) {
            ull rhi = add2(Aq[q], Bq[q]);
            ull ihi = ffma2(Cq[q], M1, Dq[q]);
            ull rlo = rp ? ffma2(Bq[q], M1, Aq[q]) : SrA[q];
            ull ilo = rp ? add2(Dq[q], Cq[q])      : SiA[q];
            float2 a = upk(rlo), b = upk(ilo);
            float2 cc = upk(rhi), d = upk(ihi);
            XF4[rp * 16 + kg * 2 + q]  = make_float4(a.x, b.x, a.y, b.y);
            XF4[jhi * 16 + kg * 2 + q] = make_float4(cc.x, d.x, cc.y, d.y);
        }
    }
}

// ---------------- stage 3: mode mix (float4 weights + prefetch) -------------
// lane: k2q = (lane&7)*4 (4 k2), bq = lane>>3 (b pair {2bq, 2bq+1}).
__global__ __launch_bounds__(256) void k_s3(const float* __restrict__ wAr,
                                            const float* __restrict__ wAi,
                                            const float* __restrict__ wBr,
                                            const float* __restrict__ wBi) {
    __shared__ ull sp[4096];              // sxr 2048 | sxi 2048 (32 KB)
    float* sxr = (float*)sp;
    float* sxi = (float*)(sp + 2048);
    int t  = threadIdx.x;
    int j  = blockIdx.x >> 3;
    int ot = blockIdx.x & 7;
    int o  = ot * 8 + (t >> 5);
    int lane = t & 31;
    int bq   = lane >> 3;                 // 0..3
    int k2q  = (lane & 7) * 4;            // 4 consecutive k2
    const float* wr; const float* wi; int jw;
    if (j < 32) { wr = wAr; wi = wAi; jw = j; }
    else        { wr = wBr; wi = wBi; jw = j - 32; }
    ull yr[2][2], yi[2][2];
#pragma unroll
    for (int bb = 0; bb < 2; bb++) { yr[bb][0]=0ull; yr[bb][1]=0ull; yi[bb][0]=0ull; yi[bb][1]=0ull; }
    const float2* XF = (const float2*)g_XF;

    for (int ic = 0; ic < 4; ic++) {
        __syncthreads();
#pragma unroll
        for (int q = 0; q < 16; q++) {
            int flat = q * 256 + t;
            int kl = flat & 31;
            int ii = (flat >> 5) & 15;
            int b  = flat >> 9;
            float2 v = XF[((size_t)(b * 64 + ic * 16 + ii) * 64 + j) * 32 + kl];
            sxr[(b * 16 + ii) * 32 + kl] = v.x;
            sxi[(b * 16 + ii) * 32 + kl] = v.y;
        }
        __syncthreads();
        size_t wb = (size_t)(ic * 16 * 64 + o) * 1024 + jw * 32 + k2q;
        float4 wre4 = *(const float4*)(wr + wb);
        float4 wim4 = *(const float4*)(wi + wb);
#pragma unroll
        for (int ii = 0; ii < 16; ii++) {
            ull wr01  = pk2(wre4.x, wre4.y),  wr23  = pk2(wre4.z, wre4.w);
            ull wi01  = pk2(wim4.x, wim4.y),  wi23  = pk2(wim4.z, wim4.w);
            ull nwi01 = pk2(-wim4.x, -wim4.y), nwi23 = pk2(-wim4.z, -wim4.w);
            if (ii < 15) {
                size_t wb2 = wb + (size_t)(ii + 1) * 65536;  // +1 i step = 64*1024 floats
                wre4 = *(const float4*)(wr + wb2);
                wim4 = *(const float4*)(wi + wb2);
            }
#pragma unroll
            for (int bb = 0; bb < 2; bb++) {
                int b = bq * 2 + bb;
                ulonglong2 xrv = *(const ulonglong2*)(sxr + (b * 16 + ii) * 32 + k2q);
                ulonglong2 xiv = *(const ulonglong2*)(sxi + (b * 16 + ii) * 32 + k2q);
                yr[bb][0] = ffma2(xrv.x, wr01, yr[bb][0]);  yr[bb][0] = ffma2(xiv.x, nwi01, yr[bb][0]);
                yr[bb][1] = ffma2(xrv.y, wr23, yr[bb][1]);  yr[bb][1] = ffma2(xiv.y, nwi23, yr[bb][1]);
                yi[bb][0] = ffma2(xrv.x, wi01, yi[bb][0]);  yi[bb][0] = ffma2(xiv.x, wr01,  yi[bb][0]);
                yi[bb][1] = ffma2(xrv.y, wi23, yi[bb][1]);  yi[bb][1] = ffma2(xiv.y, wr23,  yi[bb][1]);
            }
        }
    }
#pragma unroll
    for (int bb = 0; bb < 2; bb++) {
        int b = bq * 2 + bb;
        float2 r0 = upk(yr[bb][0]), i0 = upk(yi[bb][0]);
        float2 r1 = upk(yr[bb][1]), i1 = upk(yi[bb][1]);
        float* Yp = g_Y + (((size_t)(b * 64 + o) * 64 + j) * 32 + k2q) * 2;
        ((float4*)Yp)[0] = make_float4(r0.x, i0.x, r0.y, i0.y);
        ((float4*)Yp)[1] = make_float4(r1.x, i1.x, r1.y, i1.y);
    }
}

// ---------------- fused stage 4+5 (256 threads, occ 4 blocks/SM) ------------
// O-real plane stored NEGATED (Yb-Ya) so PBODY needs only {c,t} packs.
__global__ __launch_bounds__(256, 4) void k_s4s5(float* __restrict__ out) {
    __shared__ float zsA[64 * 68];
    __shared__ float zsB[64 * 68];
    __shared__ ull reg2u[2304];           // sY planes (E/O transformed), later F staging
    __shared__ float str[256], sti[256];
    float* reg2 = (float*)reg2u;
    int t  = threadIdx.x;
    int ch = blockIdx.x >> 1;
    int g0 = (blockIdx.x & 1) << 6;
    str[t] = g_twr[t];
    sti[t] = g_twi[t];

    float* pYr = reg2;                    // [j][36]
    float* pYi = reg2 + 2304;
    {   // stage Y -> deinterleaved planes
        const float2* Yg = (const float2*)(g_Y + (size_t)ch * 4096);
#pragma unroll
        for (int q = 0; q < 8; q++) {
            int flat = q * 256 + t;
            int jj = flat >> 5, kl = flat & 31;
            float2 v = Yg[flat];
            pYr[jj * 36 + kl] = v.x;
            pYi[jj * 36 + kl] = v.y;
        }
    }
    __syncthreads();
    {   // E/O: row a <- Ya+Yb; row 64-a real <- Yb-Ya (NEGATED O), imag <- Ya-Yb
#pragma unroll
        for (int q = 0; q < 4; q++) {
            int flat = q * 256 + t;
            if (flat < 992) {
                int a = (flat >> 5) + 1;
                int col = flat & 31;
                float ya = pYr[a * 36 + col], yb = pYr[(64 - a) * 36 + col];
                pYr[a * 36 + col] = ya + yb;
                pYr[(64 - a) * 36 + col] = yb - ya;   // negated O-real
                float za = pYi[a * 36 + col], zb = pYi[(64 - a) * 36 + col];
                pYi[a * 36 + col] = za + zb;
                pYi[(64 - a) * 36 + col] = za - zb;
            }
        }
    }
    __syncthreads();
    ull* sYr = reg2u;
    ull* sYi = reg2u + 1152;

    int hp = t >> 3;                      // 0..31
    int kg = t & 7;                       // k2 group of 4 (2 ull)
    int hA = g0 + hp;
    ull ze0r[2], ze0i[2], zo0r[2], zo0i[2];   // h = hA
    ull ze1r[2], ze1i[2], zo1r[2], zo1i[2];   // h = hA+32
#pragma unroll
    for (int q = 0; q < 2; q++) {
        ze0r[q]=0ull; ze0i[q]=0ull; zo0r[q]=0ull; zo0i[q]=0ull;
        ze1r[q]=0ull; ze1i[q]=0ull; zo1r[q]=0ull; zo1i[q]=0ull;
    }

// Zr += c*Er + t*Oi ; Zi += c*Ei + t*(-Or)   [O-real pre-negated in smem]
#define PBODY(A, R0, I0, R1, I1) { \
    int ia = ((A) * hA) & 255; \
    int ib = (ia + (A) * 32) & 255; \
    float c0 = str[ia], t0 = sti[ia]; \
    float c1 = str[ib], t1 = sti[ib]; \
    ull c0p = pk2(c0, c0), t0p = pk2(t0, t0); \
    ull c1p = pk2(c1, c1), t1p = pk2(t1, t1); \
    ulonglong2 er  = *(const ulonglong2*)(sYr + (A) * 18 + kg * 2); \
    ulonglong2 ei  = *(const ulonglong2*)(sYi + (A) * 18 + kg * 2); \
    ulonglong2 nor = *(const ulonglong2*)(sYr + (64 - (A)) * 18 + kg * 2); \
    ulonglong2 oii = *(const ulonglong2*)(sYi + (64 - (A)) * 18 + kg * 2); \
    R0[0] = ffma2(er.x, c0p, R0[0]);  R0[0] = ffma2(oii.x, t0p, R0[0]); \
    I0[0] = ffma2(ei.x, c0p, I0[0]);  I0[0] = ffma2(nor.x, t0p, I0[0]); \
    R0[1] = ffma2(er.y, c0p, R0[1]);  R0[1] = ffma2(oii.y, t0p, R0[1]); \
    I0[1] = ffma2(ei.y, c0p, I0[1]);  I0[1] = ffma2(nor.y, t0p, I0[1]); \
    R1[0] = ffma2(er.x, c1p, R1[0]);  R1[0] = ffma2(oii.x, t1p, R1[0]); \
    I1[0] = ffma2(ei.x, c1p, I1[0]);  I1[0] = ffma2(nor.x, t1p, I1[0]); \
    R1[1] = ffma2(er.y, c1p, R1[1]);  R1[1] = ffma2(oii.y, t1p, R1[1]); \
    I1[1] = ffma2(ei.y, c1p, I1[1]);  I1[1] = ffma2(nor.y, t1p, I1[1]); }

#pragma unroll 3
    for (int ap = 0; ap < 15; ap++) {
        PBODY(2 * ap + 1, zo0r, zo0i, zo1r, zo1i)
        PBODY(2 * ap + 2, ze0r, ze0i, ze1r, ze1i)
    }
    PBODY(31, zo0r, zo0i, zo1r, zo1i)
#undef PBODY

    {   // j=0 (k1=0, even): constant contribution Y0 to both h regs
        ulonglong2 y0r = *(const ulonglong2*)(sYr + kg * 2);
        ulonglong2 y0i = *(const ulonglong2*)(sYi + kg * 2);
        ze0r[0] = add2(ze0r[0], y0r.x); ze0r[1] = add2(ze0r[1], y0r.y);
        ze0i[0] = add2(ze0i[0], y0i.x); ze0i[1] = add2(ze0i[1], y0i.y);
        ze1r[0] = add2(ze1r[0], y0r.x); ze1r[1] = add2(ze1r[1], y0r.y);
        ze1i[0] = add2(ze1i[0], y0i.x); ze1i[1] = add2(ze1i[1], y0i.y);
    }
    {   // j=32 (k1=-32, even): e^{-i32h} -- same angle for hA and hA+32
        int i32 = (32 * hA) & 255;
        float c = str[i32], tv = sti[i32];
        ull cp = pk2(c, c), tp = pk2(tv, tv), np = pk2(-tv, -tv);
        ulonglong2 y2r = *(const ulonglong2*)(sYr + 32 * 18 + kg * 2);
        ulonglong2 y2i = *(const ulonglong2*)(sYi + 32 * 18 + kg * 2);
#pragma unroll
        for (int q = 0; q < 2; q++) {
            ull r2v = q ? y2r.y : y2r.x;
            ull i2v = q ? y2i.y : y2i.x;
            ze0r[q] = ffma2(r2v, cp, ze0r[q]);  ze0r[q] = ffma2(i2v, np, ze0r[q]);
            ze0i[q] = ffma2(i2v, cp, ze0i[q]);  ze0i[q] = ffma2(r2v, tp, ze0i[q]);
            ze1r[q] = ffma2(r2v, cp, ze1r[q]);  ze1r[q] = ffma2(i2v, np, ze1r[q]);
            ze1i[q] = ffma2(i2v, cp, ze1i[q]);  ze1i[q] = ffma2(r2v, tp, ze1i[q]);
        }
    }

    // combine parity partials -> both h tiles
    {
        const ull M1 = pk2(-1.f, -1.f);
#pragma unroll
        for (int q = 0; q < 2; q++) {
            int c2 = 2 * (kg * 4 + 2 * q);
            float2 ra, ia, rb, ib;
            ra = upk(add2(ze0r[q], zo0r[q]));  ia = upk(add2(ze0i[q], zo0i[q]));
            rb = upk(ffma2(zo0r[q], M1, ze0r[q]));  ib = upk(ffma2(zo0i[q], M1, ze0i[q]));
            zsA[c2 * 68 + hp]       = ra.x; zsA[(c2 + 1) * 68 + hp] = ia.x;
            zsA[(c2 + 2) * 68 + hp] = ra.y; zsA[(c2 + 3) * 68 + hp] = ia.y;
            zsB[c2 * 68 + hp]       = rb.x; zsB[(c2 + 1) * 68 + hp] = ib.x;
            zsB[(c2 + 2) * 68 + hp] = rb.y; zsB[(c2 + 3) * 68 + hp] = ib.y;
            ra = upk(add2(ze1r[q], zo1r[q]));  ia = upk(add2(ze1i[q], zo1i[q]));
            rb = upk(ffma2(zo1r[q], M1, ze1r[q]));  ib = upk(ffma2(zo1i[q], M1, ze1i[q]));
            zsA[c2 * 68 + hp + 32]       = ra.x; zsA[(c2 + 1) * 68 + hp + 32] = ia.x;
            zsA[(c2 + 2) * 68 + hp + 32] = ra.y; zsA[(c2 + 3) * 68 + hp + 32] = ia.y;
            zsB[c2 * 68 + hp + 32]       = rb.x; zsB[(c2 + 1) * 68 + hp + 32] = ib.x;
            zsB[(c2 + 2) * 68 + hp + 32] = rb.y; zsB[(c2 + 3) * 68 + hp + 32] = ib.y;
        }
    }
    __syncthreads();

    // w=128 columns for both tiles
    if (t < 128) {
        int tile = t >> 6;
        int row  = t & 63;
        const float* zz = tile ? zsB : zsA;
        float s = zz[row];
#pragma unroll
        for (int k2 = 1; k2 < 32; k2++)
            s += ((k2 & 1) ? -2.f : 2.f) * zz[2 * k2 * 68 + row];
        out[((size_t)ch * 256 + g0 + tile * 128 + row) * 256 + 128] = s * (1.f / 65536.f);
    }

    // Phase B: folded inverse-w, BOTH tiles per k2 step (shared F loads).
    int hg = t >> 4;
    int wg = t & 15;
    const float4* FcG = (const float4*)g_Fc;
    const float4* FsG = (const float4*)g_Fs;
    const ull M1 = pk2(-1.f, -1.f);
    for (int wt = 0; wt < 4; wt++) {
        __syncthreads();
        {   // stage Fc/Fs chunk: 32 k2 x 32 w' each (one float4 per thread)
            int k2s = t >> 3, u = t & 7;
            ((float4*)reg2)[k2s * 8 + u]       = FcG[k2s * 32 + wt * 8 + u];
            ((float4*)reg2)[256 + k2s * 8 + u] = FsG[k2s * 32 + wt * 8 + u];
        }
        __syncthreads();
        ull PA[4], QA[4], PB[4], QB[4];
#pragma unroll
        for (int q = 0; q < 4; q++) { PA[q]=0ull; QA[q]=0ull; PB[q]=0ull; QB[q]=0ull; }
#pragma unroll 4
        for (int k2 = 0; k2 < 32; k2++) {
            float4 aA = *(const float4*)(zsA + (2 * k2) * 68 + hg * 4);
            float4 bA = *(const float4*)(zsA + (2 * k2 + 1) * 68 + hg * 4);
            float4 aB = *(const float4*)(zsB + (2 * k2) * 68 + hg * 4);
            float4 bB = *(const float4*)(zsB + (2 * k2 + 1) * 68 + hg * 4);
            ull f = *(const ull*)(reg2 + k2 * 32 + wg * 2);
            ull g = *(const ull*)(reg2 + 1024 + k2 * 32 + wg * 2);
            ull pr, pi;
#define BROW2(R, AVA, BVA, AVB, BVB) \
            pr = pk2(AVA, AVA); pi = pk2(BVA, BVA); \
            PA[R] = ffma2(pr, f, PA[R]); QA[R] = ffma2(pi, g, QA[R]); \
            pr = pk2(AVB, AVB); pi = pk2(BVB, BVB); \
            PB[R] = ffma2(pr, f, PB[R]); QB[R] = ffma2(pi, g, QB[R]);
            BROW2(0, aA.x, bA.x, aB.x, bB.x)
            BROW2(1, aA.y, bA.y, aB.y, bB.y)
            BROW2(2, aA.z, bA.z, aB.z, bB.z)
            BROW2(3, aA.w, bA.w, aB.w, bB.w)
#undef BROW2
        }
        int wbase = wt * 32 + wg * 2;
#pragma unroll
        for (int r = 0; r < 4; r++) {
            int hloc = hg * 4 + r;
            {   // tile A (h rows g0..g0+63)
                float* orow = out + ((size_t)ch * 256 + g0 + hloc) * 256;
                ull Av = add2(PA[r], QA[r]);
                ull Bv = ffma2(QA[r], M1, PA[r]);
                float2 fa = upk(Av), fb = upk(Bv);
                *(float2*)(orow + wbase) = fa;
#pragma unroll
                for (int i = 0; i < 2; i++) {
                    int wv = wbase + i;
                    if (wv) orow[256 - wv] = i ? fb.y : fb.x;
                }
            }
            {   // tile B (h rows g0+128..g0+191)
                float* orow = out + ((size_t)ch * 256 + g0 + 128 + hloc) * 256;
                ull Av = add2(PB[r], QB[r]);
                ull Bv = ffma2(QB[r], M1, PB[r]);
                float2 fa = upk(Av), fb = upk(Bv);
                *(float2*)(orow + wbase) = fa;
#pragma unroll
                for (int i = 0; i < 2; i++) {
                    int wv = wbase + i;
                    if (wv) orow[256 - wv] = i ? fb.y : fb.x;
                }
            }
        }
    }
}

// ---------------------------------------------------------------------------
extern "C" void kernel_launch(void* const* d_in, const int* in_sizes, int n_in,
                              void* d_out, int out_size) {
    const float* x   = (const float*)d_in[0];
    const float* w1r = (const float*)d_in[1];
    const float* w1i = (const float*)d_in[2];
    const float* w2r = (const float*)d_in[3];
    const float* w2i = (const float*)d_in[4];
    const float* w3r = (const float*)d_in[5];
    const float* w3i = (const float*)d_in[6];
    const float* w4r = (const float*)d_in[7];
    const float* w4i = (const float*)d_in[8];
    float* out = (float*)d_out;

    k_init<<<34, 256>>>();

    // ---- branch x ----
    k_s1s2<<<512, 256>>>(x, 0);
    k_s3<<<512, 256>>>(w1r, w1i, w2r, w2i);
    k_s4s5<<<1024, 256>>>(out);

    // ---- branch x^T ----
    k_s1s2<<<512, 256>>>(x, 1);
    k_s3<<<512, 256>>>(w3r, w3i, w4r, w4i);
    k_s4s5<<<1024, 256>>>(out + (size_t)NCH * 65536);
}